// round 3
// baseline (speedup 1.0000x reference)
#include <cuda_runtime.h>

#define B_ 16
#define T_ 8
#define C_ 2048
#define H_ 16
#define D_ 128
#define MAXSEQ 4096
#define QKV_N (3*C_)   // 6144
#define M_ (B_*T_)     // 128

// Scratch (no allocations allowed) -------------------------------------------
__device__ float g_qkv[M_ * QKV_N];   // [b*T+t][3C]  q|k|v packed
__device__ float g_y[M_ * C_];        // attention output [b*T+t][h*D+d]

// ---------------------------------------------------------------------------
// out[m][n] = bias[n]   (vectorized float4; M*N divisible by 4, N%4==0)
__global__ void bias_init_kernel(float* __restrict__ C, const float* __restrict__ bias,
                                 int M, int N) {
    int i = blockIdx.x * blockDim.x + threadIdx.x;
    int total = (M * N) >> 2;
    if (i < total) {
        int n = (i << 2) % N;
        ((float4*)C)[i] = *(const float4*)(bias + n);
    }
}

// ---------------------------------------------------------------------------
// C[m][n] += sum_k A[m][k]*W[k][n]  over k in [k0, k0+kLen)
// BM=BN=64, BK=16, 256 threads, 4x4 thread tile, atomicAdd epilogue (RED.ADD).
__global__ void sgemm_atomic(const float* __restrict__ A, const float* __restrict__ W,
                             float* __restrict__ Cmat, int M, int N, int K, int kLen) {
    __shared__ float As[16][68];   // As[k][m] (transposed)
    __shared__ float Bs[16][68];   // Bs[k][n]
    int tid = threadIdx.x;
    int tx = tid & 15, ty = tid >> 4;
    int n0 = blockIdx.x * 64;
    int m0 = blockIdx.y * 64;
    int k0 = blockIdx.z * kLen;

    float acc[4][4];
    #pragma unroll
    for (int i = 0; i < 4; i++)
        #pragma unroll
        for (int j = 0; j < 4; j++) acc[i][j] = 0.f;

    int ar = tid >> 2, ac = tid & 3;    // A tile loader: row m=ar, k-chunk ac
    int br = tid >> 4, bc = tid & 15;   // B tile loader: k=br, n-chunk bc

    for (int kk = 0; kk < kLen; kk += 16) {
        float4 a = *(const float4*)(A + (size_t)(m0 + ar) * K + (k0 + kk + ac * 4));
        As[ac*4+0][ar] = a.x;
        As[ac*4+1][ar] = a.y;
        As[ac*4+2][ar] = a.z;
        As[ac*4+3][ar] = a.w;
        *(float4*)&Bs[br][bc*4] =
            *(const float4*)(W + (size_t)(k0 + kk + br) * N + (n0 + bc * 4));
        __syncthreads();
        #pragma unroll
        for (int k = 0; k < 16; k++) {
            float4 a4 = *(float4*)&As[k][ty*4];
            float4 b4 = *(float4*)&Bs[k][tx*4];
            float av[4] = {a4.x, a4.y, a4.z, a4.w};
            float bv[4] = {b4.x, b4.y, b4.z, b4.w};
            #pragma unroll
            for (int i = 0; i < 4; i++)
                #pragma unroll
                for (int j = 0; j < 4; j++)
                    acc[i][j] += av[i] * bv[j];
        }
        __syncthreads();
    }
    #pragma unroll
    for (int i = 0; i < 4; i++) {
        size_t mrow = (size_t)(m0 + ty*4 + i) * N + n0 + tx*4;
        #pragma unroll
        for (int j = 0; j < 4; j++)
            atomicAdd(&Cmat[mrow + j], acc[i][j]);
    }
}

// ---------------------------------------------------------------------------
// Flash-style attention, one CTA per (b,h). 256 threads (8 warps).
// Online softmax over S tiles of 128. Per-warp partial fp32 accumulators.
// smem: q[8][128] | tile[128][132] (K then V) | p[8][132] | m[8] l[8] c[8]
#define TILE_S 128
#define TSTRIDE 132
#define SMEM_FLOATS (1024 + 128*TSTRIDE + 8*TSTRIDE + 24)

__global__ void attn_kernel(const float* __restrict__ k_cache,
                            const float* __restrict__ v_cache,
                            const int* __restrict__ sp_ptr,
                            const int* __restrict__ causal_ptr) {
    extern __shared__ float sm[];
    float* q    = sm;                       // 8*128
    float* tile = sm + 1024;                // 128*132
    float* p    = tile + 128*TSTRIDE;       // 8*132
    float* mbuf = p + 8*TSTRIDE;            // 8
    float* lbuf = mbuf + 8;                 // 8
    float* cbuf = lbuf + 8;                 // 8

    int tid  = threadIdx.x;
    int lane = tid & 31;
    int w    = tid >> 5;
    int bh   = blockIdx.x;
    int b = bh >> 4, h = bh & 15;
    int sp = *sp_ptr;
    int causal = *causal_ptr;
    int S = sp + T_;

    // load q (pre-scaled by 1/sqrt(D))
    {
        int t = tid >> 5;
        int d = (tid & 31) * 4;
        float4 v4 = *(const float4*)(g_qkv + (size_t)(b*T_ + t)*QKV_N + h*D_ + d);
        const float sc = 0.08838834764831845f; // 1/sqrt(128)
        v4.x *= sc; v4.y *= sc; v4.z *= sc; v4.w *= sc;
        *(float4*)&q[t*128 + d] = v4;
    }
    if (tid < 8) { mbuf[tid] = -1e30f; lbuf[tid] = 0.f; }

    float4 acc[8];
    #pragma unroll
    for (int t = 0; t < 8; t++) acc[t] = make_float4(0.f, 0.f, 0.f, 0.f);

    __syncthreads();

    int row  = tid >> 1, half = tid & 1;     // tile loader mapping
    int t0   = (tid >> 6) * 2;               // score-phase: 2 t-rows per thread
    int sl   = tid & 63;                     // score-phase: s and s+64

    for (int s0 = 0; s0 < S; s0 += TILE_S) {
        // ---- load K tile (cache rows or fresh rows from g_qkv) ----
        {
            int s = s0 + row;
            bool valid = s < S;
            const float* src;
            if (s < sp) src = k_cache + ((size_t)(b*H_ + h) * MAXSEQ + s) * D_;
            else        src = g_qkv + (size_t)(b*T_ + (s - sp)) * QKV_N + C_ + h*D_;
            float* dst = tile + row*TSTRIDE + half*64;
            const float* s2 = src + half*64;
            #pragma unroll
            for (int j = 0; j < 16; j++) {
                float4 v4 = valid ? *(const float4*)(s2 + j*4)
                                  : make_float4(0.f, 0.f, 0.f, 0.f);
                *(float4*)(dst + j*4) = v4;
            }
        }
        __syncthreads();
        // ---- scores: 2 t x 2 s per thread ----
        {
            float a00 = 0.f, a01 = 0.f, a10 = 0.f, a11 = 0.f;
            const float* q0 = q + t0*128;
            const float* q1 = q + (t0+1)*128;
            const float* kA = tile + sl*TSTRIDE;
            const float* kB = tile + (sl+64)*TSTRIDE;
            #pragma unroll 8
            for (int dc = 0; dc < 128; dc += 4) {
                float4 qa = *(const float4*)(q0 + dc);
                float4 qb = *(const float4*)(q1 + dc);
                float4 ka = *(const float4*)(kA + dc);
                float4 kb = *(const float4*)(kB + dc);
                a00 += qa.x*ka.x + qa.y*ka.y + qa.z*ka.z + qa.w*ka.w;
                a01 += qa.x*kb.x + qa.y*kb.y + qa.z*kb.z + qa.w*kb.w;
                a10 += qb.x*ka.x + qb.y*ka.y + qb.z*ka.z + qb.w*ka.w;
                a11 += qb.x*kb.x + qb.y*kb.y + qb.z*kb.z + qb.w*kb.w;
            }
            p[t0*TSTRIDE + sl]          = a00;
            p[t0*TSTRIDE + sl + 64]     = a01;
            p[(t0+1)*TSTRIDE + sl]      = a10;
            p[(t0+1)*TSTRIDE + sl + 64] = a11;
        }
        __syncthreads();
        // ---- online softmax: warp w owns row t=w ----
        {
            int t = w;
            float vj[4];
            #pragma unroll
            for (int j = 0; j < 4; j++) {
                int sl_ = lane + j*32;
                int sg  = s0 + sl_;
                float v = p[t*TSTRIDE + sl_];
                bool valid = (sg < S) && (!causal || sg <= t);
                vj[j] = valid ? v : -1e30f;
            }
            float mx = fmaxf(fmaxf(vj[0], vj[1]), fmaxf(vj[2], vj[3]));
            #pragma unroll
            for (int o = 16; o > 0; o >>= 1)
                mx = fmaxf(mx, __shfl_xor_sync(0xffffffffu, mx, o));
            float mold = mbuf[t];
            float mnew = fmaxf(mold, mx);
            float sum = 0.f;
            #pragma unroll
            for (int j = 0; j < 4; j++) {
                float e = (vj[j] < -1e29f) ? 0.f : __expf(vj[j] - mnew);
                p[t*TSTRIDE + lane + j*32] = e;
                sum += e;
            }
            #pragma unroll
            for (int o = 16; o > 0; o >>= 1)
                sum += __shfl_xor_sync(0xffffffffu, sum, o);
            if (lane == 0) {
                float c = __expf(mold - mnew);
                cbuf[t] = c;
                lbuf[t] = lbuf[t] * c + sum;
                mbuf[t] = mnew;
            }
        }
        __syncthreads();
        // ---- rescale per-warp partial acc by correction c[t] ----
        {
            #pragma unroll
            for (int t = 0; t < 8; t++) {
                float c = cbuf[t];
                acc[t].x *= c; acc[t].y *= c; acc[t].z *= c; acc[t].w *= c;
            }
        }
        // ---- load V tile over K tile ----
        {
            int s = s0 + row;
            bool valid = s < S;
            const float* src;
            if (s < sp) src = v_cache + ((size_t)(b*H_ + h) * MAXSEQ + s) * D_;
            else        src = g_qkv + (size_t)(b*T_ + (s - sp)) * QKV_N + 2*C_ + h*D_;
            float* dst = tile + row*TSTRIDE + half*64;
            const float* s2 = src + half*64;
            #pragma unroll
            for (int j = 0; j < 16; j++) {
                float4 v4 = valid ? *(const float4*)(s2 + j*4)
                                  : make_float4(0.f, 0.f, 0.f, 0.f);
                *(float4*)(dst + j*4) = v4;
            }
        }
        __syncthreads();
        // ---- P @ V : warp w handles s = w, w+8, ... (16 iters) ----
        {
            for (int i = 0; i < 16; i++) {
                int s = w + i*8;
                float4 v4 = *(const float4*)(tile + s*TSTRIDE + lane*4);
                #pragma unroll
                for (int t = 0; t < 8; t++) {
                    float pv = p[t*TSTRIDE + s];
                    acc[t].x += pv*v4.x; acc[t].y += pv*v4.y;
                    acc[t].z += pv*v4.z; acc[t].w += pv*v4.w;
                }
            }
        }
        __syncthreads();
    }

    // ---- combine 8 per-warp partials, normalize by l, write y ----
    #pragma unroll
    for (int t = 0; t < 8; t++)
        *(float4*)(tile + (w*8 + t)*128 + lane*4) = acc[t];
    __syncthreads();
    {
        int t  = tid >> 5;
        int dg = (tid & 31) * 4;
        float4 sv = make_float4(0.f, 0.f, 0.f, 0.f);
        #pragma unroll
        for (int ww = 0; ww < 8; ww++) {
            float4 a = *(float4*)(tile + (ww*8 + t)*128 + dg);
            sv.x += a.x; sv.y += a.y; sv.z += a.z; sv.w += a.w;
        }
        float l = lbuf[t];
        float inv = (l > 0.f) ? (1.0f / l) : 0.f;
        sv.x *= inv; sv.y *= inv; sv.z *= inv; sv.w *= inv;
        *(float4*)(g_y + (size_t)(b*T_ + t)*C_ + h*D_ + dg) = sv;
    }
}

// ---------------------------------------------------------------------------
extern "C" void kernel_launch(void* const* d_in, const int* in_sizes, int n_in,
                              void* d_out, int out_size) {
    const float* x       = (const float*)d_in[0];
    const float* k_cache = (const float*)d_in[1];
    const float* v_cache = (const float*)d_in[2];
    const float* w_attn  = (const float*)d_in[3];
    const float* b_attn  = (const float*)d_in[4];
    const float* w_proj  = (const float*)d_in[5];
    const float* b_proj  = (const float*)d_in[6];
    const int*   sp      = (const int*)d_in[7];
    const int*   ic      = (const int*)d_in[8];
    float* out = (float*)d_out;

    float *qkv, *y;
    cudaGetSymbolAddress((void**)&qkv, g_qkv);
    cudaGetSymbolAddress((void**)&y, g_y);

    cudaFuncSetAttribute(attn_kernel, cudaFuncAttributeMaxDynamicSharedMemorySize,
                         SMEM_FLOATS * 4);

    // 1) qkv = x @ w_attn + b_attn
    bias_init_kernel<<<(M_*QKV_N/4 + 255)/256, 256>>>(qkv, b_attn, M_, QKV_N);
    sgemm_atomic<<<dim3(QKV_N/64, M_/64, 1), 256>>>(x, w_attn, qkv, M_, QKV_N, C_, C_);

    // 2) attention (reads cache + fresh K/V rows from g_qkv) -> g_y
    attn_kernel<<<B_*H_, 256, SMEM_FLOATS * 4>>>(k_cache, v_cache, sp, ic);

    // 3) out = y @ w_proj + b_proj  (split-K=2 for occupancy)
    bias_init_kernel<<<(M_*C_/4 + 255)/256, 256>>>(out, b_proj, M_, C_);
    sgemm_atomic<<<dim3(C_/64, M_/64, 2), 256>>>(y, w_proj, out, M_, C_, C_, C_/2);
}

// round 4
// speedup vs baseline: 1.4471x; 1.4471x over previous
#include <cuda_runtime.h>
#include <cstdint>

#define B_ 16
#define T_ 8
#define C_ 2048
#define H_ 16
#define D_ 128
#define MAXSEQ 4096
#define QKV_N (3*C_)   // 6144
#define M_ (B_*T_)     // 128

// Scratch (no allocations allowed) -------------------------------------------
__device__ float g_qkv[M_ * QKV_N];   // [b*T+t][3C]  q|k|v packed
__device__ float g_y[M_ * C_];        // attention output [b*T+t][h*D+d]

// ---------------------------------------------------------------------------
__global__ void bias_init_kernel(float* __restrict__ C, const float* __restrict__ bias,
                                 int M, int N) {
    int i = blockIdx.x * blockDim.x + threadIdx.x;
    int total = (M * N) >> 2;
    if (i < total) {
        int n = (i << 2) % N;
        ((float4*)C)[i] = *(const float4*)(bias + n);
    }
}

// ---------------------------------------------------------------------------
// C[m][n] += sum_k A[m][k]*W[k][n]  over k in [k0, k0+kLen)
// BM=BN=64, BK=16, 256 threads, 4x4 thread tile, atomicAdd epilogue.
__global__ void sgemm_atomic(const float* __restrict__ A, const float* __restrict__ W,
                             float* __restrict__ Cmat, int M, int N, int K, int kLen) {
    __shared__ float As[16][68];
    __shared__ float Bs[16][68];
    int tid = threadIdx.x;
    int tx = tid & 15, ty = tid >> 4;
    int n0 = blockIdx.x * 64;
    int m0 = blockIdx.y * 64;
    int k0 = blockIdx.z * kLen;

    float acc[4][4];
    #pragma unroll
    for (int i = 0; i < 4; i++)
        #pragma unroll
        for (int j = 0; j < 4; j++) acc[i][j] = 0.f;

    int ar = tid >> 2, ac = tid & 3;
    int br = tid >> 4, bc = tid & 15;

    for (int kk = 0; kk < kLen; kk += 16) {
        float4 a = *(const float4*)(A + (size_t)(m0 + ar) * K + (k0 + kk + ac * 4));
        As[ac*4+0][ar] = a.x;
        As[ac*4+1][ar] = a.y;
        As[ac*4+2][ar] = a.z;
        As[ac*4+3][ar] = a.w;
        *(float4*)&Bs[br][bc*4] =
            *(const float4*)(W + (size_t)(k0 + kk + br) * N + (n0 + bc * 4));
        __syncthreads();
        #pragma unroll
        for (int k = 0; k < 16; k++) {
            float4 a4 = *(float4*)&As[k][ty*4];
            float4 b4 = *(float4*)&Bs[k][tx*4];
            float av[4] = {a4.x, a4.y, a4.z, a4.w};
            float bv[4] = {b4.x, b4.y, b4.z, b4.w};
            #pragma unroll
            for (int i = 0; i < 4; i++)
                #pragma unroll
                for (int j = 0; j < 4; j++)
                    acc[i][j] += av[i] * bv[j];
        }
        __syncthreads();
    }
    #pragma unroll
    for (int i = 0; i < 4; i++) {
        size_t mrow = (size_t)(m0 + ty*4 + i) * N + n0 + tx*4;
        #pragma unroll
        for (int j = 0; j < 4; j++)
            atomicAdd(&Cmat[mrow + j], acc[i][j]);
    }
}

// ---------------------------------------------------------------------------
// Flash attention with tf32 mma.sync.m16n8k8 (m padded 8->16, zero rows).
// One CTA per (b,h), 8 warps. Warp w owns 16 s-cols (scores) / 16 d-cols (PV).
#define QS 132
#define TS 132
#define SMEM_FLOATS (16*QS + 128*TS + 16*TS + 24)

__device__ __forceinline__ uint32_t f2tf(float x) {
    uint32_t r; asm("cvt.rna.tf32.f32 %0, %1;" : "=r"(r) : "f"(x)); return r;
}

__device__ __forceinline__ void mma8(float* d, uint32_t a0, uint32_t a2,
                                     uint32_t b0, uint32_t b1) {
    const uint32_t z = 0;
    asm volatile(
        "mma.sync.aligned.m16n8k8.row.col.f32.tf32.tf32.f32 "
        "{%0,%1,%2,%3}, {%4,%5,%6,%7}, {%8,%9}, {%0,%1,%2,%3};"
        : "+f"(d[0]), "+f"(d[1]), "+f"(d[2]), "+f"(d[3])
        : "r"(a0), "r"(z), "r"(a2), "r"(z), "r"(b0), "r"(b1));
}

__global__ void __launch_bounds__(256, 2)
attn_kernel(const float* __restrict__ k_cache,
            const float* __restrict__ v_cache,
            const int* __restrict__ sp_ptr,
            const int* __restrict__ causal_ptr) {
    extern __shared__ float sm[];
    float* q    = sm;                  // 16 x 132 (rows 8-15 zero)
    float* tile = sm + 16*QS;          // 128 x 132 (K then V)
    float* p    = tile + 128*TS;       // 16 x 132 (rows 8-15 zero)
    float* mbuf = p + 16*TS;
    float* lbuf = mbuf + 8;
    float* cbuf = lbuf + 8;

    int tid  = threadIdx.x;
    int lane = tid & 31;
    int w    = tid >> 5;
    int b = blockIdx.x >> 4, h = blockIdx.x & 15;
    int sp = *sp_ptr;
    int causal = *causal_ptr;
    int S = sp + T_;
    int g = lane >> 2, c4 = lane & 3;

    for (int i = tid; i < 16*QS; i += 256) q[i] = 0.f;
    for (int i = tid; i < 16*TS; i += 256) p[i] = 0.f;
    if (tid < 8) { mbuf[tid] = -1e30f; lbuf[tid] = 0.f; }
    __syncthreads();

    // q rows 0-7, pre-scaled, tf32-rounded
    {
        int t = tid >> 5;
        int d = lane * 4;
        float4 v4 = *(const float4*)(g_qkv + (size_t)(b*T_ + t)*QKV_N + h*D_ + d);
        const float sc = 0.08838834764831845f;   // 1/sqrt(128)
        q[t*QS + d + 0] = __uint_as_float(f2tf(v4.x * sc));
        q[t*QS + d + 1] = __uint_as_float(f2tf(v4.y * sc));
        q[t*QS + d + 2] = __uint_as_float(f2tf(v4.z * sc));
        q[t*QS + d + 3] = __uint_as_float(f2tf(v4.w * sc));
    }
    __syncthreads();

    float oacc[2][4];
    #pragma unroll
    for (int nt = 0; nt < 2; nt++)
        #pragma unroll
        for (int j = 0; j < 4; j++) oacc[nt][j] = 0.f;

    for (int s0 = 0; s0 < S; s0 += 128) {
        // ---- K tile load: warp w loads rows i*8+w, lane-contiguous float4 ----
        #pragma unroll
        for (int i = 0; i < 16; i++) {
            int r = i*8 + w;
            int s = s0 + r;
            float4 v4 = make_float4(0.f, 0.f, 0.f, 0.f);
            if (s < S) {
                const float* src = (s < sp)
                    ? k_cache + ((size_t)(b*H_ + h)*MAXSEQ + s)*D_
                    : g_qkv + (size_t)(b*T_ + (s - sp))*QKV_N + C_ + h*D_;
                v4 = *(const float4*)(src + lane*4);
            }
            *(float4*)(tile + r*TS + lane*4) = v4;
        }
        __syncthreads();

        // ---- scores: warp w -> s-cols [16w, 16w+16) ----
        {
            float sc2[2][4];
            #pragma unroll
            for (int nt = 0; nt < 2; nt++)
                #pragma unroll
                for (int j = 0; j < 4; j++) sc2[nt][j] = 0.f;
            #pragma unroll
            for (int ks = 0; ks < 16; ks++) {
                uint32_t a0 = __float_as_uint(q[g*QS + 8*ks + c4]);
                uint32_t a2 = __float_as_uint(q[g*QS + 8*ks + c4 + 4]);
                #pragma unroll
                for (int nt = 0; nt < 2; nt++) {
                    const float* kb = tile + (size_t)(16*w + 8*nt + g)*TS + 8*ks + c4;
                    mma8(sc2[nt], a0, a2,
                         __float_as_uint(kb[0]), __float_as_uint(kb[4]));
                }
            }
            #pragma unroll
            for (int nt = 0; nt < 2; nt++)
                *(float2*)(p + g*TS + 16*w + 8*nt + 2*c4) =
                    make_float2(sc2[nt][0], sc2[nt][1]);
        }
        __syncthreads();

        // ---- online softmax: warp w owns row t=w ----
        {
            int t = w;
            float vj[4];
            #pragma unroll
            for (int j = 0; j < 4; j++) {
                int sl_ = lane + j*32;
                int sg  = s0 + sl_;
                float v = p[t*TS + sl_];
                bool valid = (sg < S) && (!causal || sg <= t);
                vj[j] = valid ? v : -1e30f;
            }
            float mx = fmaxf(fmaxf(vj[0], vj[1]), fmaxf(vj[2], vj[3]));
            #pragma unroll
            for (int o = 16; o > 0; o >>= 1)
                mx = fmaxf(mx, __shfl_xor_sync(0xffffffffu, mx, o));
            float mold = mbuf[t];
            float mnew = fmaxf(mold, mx);
            float sum = 0.f;
            #pragma unroll
            for (int j = 0; j < 4; j++) {
                float e = (vj[j] < -1e29f) ? 0.f : __expf(vj[j] - mnew);
                float er = __uint_as_float(f2tf(e));   // round to tf32 for PV
                p[t*TS + lane + j*32] = er;
                sum += er;
            }
            #pragma unroll
            for (int o = 16; o > 0; o >>= 1)
                sum += __shfl_xor_sync(0xffffffffu, sum, o);
            if (lane == 0) {
                float cc = __expf(mold - mnew);
                cbuf[t] = cc;
                lbuf[t] = lbuf[t] * cc + sum;
                mbuf[t] = mnew;
            }
        }
        __syncthreads();

        // ---- rescale O fragments (rows 0-7 live in regs 0,1) ----
        {
            float cf = cbuf[g];
            #pragma unroll
            for (int nt = 0; nt < 2; nt++) { oacc[nt][0] *= cf; oacc[nt][1] *= cf; }
        }

        // ---- V tile load (overlay) ----
        #pragma unroll
        for (int i = 0; i < 16; i++) {
            int r = i*8 + w;
            int s = s0 + r;
            float4 v4 = make_float4(0.f, 0.f, 0.f, 0.f);
            if (s < S) {
                const float* src = (s < sp)
                    ? v_cache + ((size_t)(b*H_ + h)*MAXSEQ + s)*D_
                    : g_qkv + (size_t)(b*T_ + (s - sp))*QKV_N + 2*C_ + h*D_;
                v4 = *(const float4*)(src + lane*4);
            }
            *(float4*)(tile + r*TS + lane*4) = v4;
        }
        __syncthreads();

        // ---- PV: warp w -> d-cols [16w, 16w+16) ----
        #pragma unroll
        for (int ks = 0; ks < 16; ks++) {
            uint32_t a0 = __float_as_uint(p[g*TS + 8*ks + c4]);
            uint32_t a2 = __float_as_uint(p[g*TS + 8*ks + c4 + 4]);
            #pragma unroll
            for (int nt = 0; nt < 2; nt++) {
                int n0 = 16*w + 8*nt;
                uint32_t b0 = __float_as_uint(tile[(size_t)(8*ks + c4)*TS + n0 + g]);
                uint32_t b1 = __float_as_uint(tile[(size_t)(8*ks + c4 + 4)*TS + n0 + g]);
                mma8(oacc[nt], a0, a2, b0, b1);
            }
        }
        __syncthreads();
    }

    // ---- epilogue: normalize, direct store (no cross-warp reduce needed) ----
    {
        float l = lbuf[g];
        float inv = (l > 0.f) ? (1.f / l) : 0.f;
        #pragma unroll
        for (int nt = 0; nt < 2; nt++) {
            int d0 = 16*w + 8*nt + 2*c4;
            float2 o = make_float2(oacc[nt][0]*inv, oacc[nt][1]*inv);
            *(float2*)(g_y + (size_t)(b*T_ + g)*C_ + h*D_ + d0) = o;
        }
    }
}

// ---------------------------------------------------------------------------
extern "C" void kernel_launch(void* const* d_in, const int* in_sizes, int n_in,
                              void* d_out, int out_size) {
    const float* x       = (const float*)d_in[0];
    const float* k_cache = (const float*)d_in[1];
    const float* v_cache = (const float*)d_in[2];
    const float* w_attn  = (const float*)d_in[3];
    const float* b_attn  = (const float*)d_in[4];
    const float* w_proj  = (const float*)d_in[5];
    const float* b_proj  = (const float*)d_in[6];
    const int*   sp      = (const int*)d_in[7];
    const int*   ic      = (const int*)d_in[8];
    float* out = (float*)d_out;

    float *qkv, *y;
    cudaGetSymbolAddress((void**)&qkv, g_qkv);
    cudaGetSymbolAddress((void**)&y, g_y);

    cudaFuncSetAttribute(attn_kernel, cudaFuncAttributeMaxDynamicSharedMemorySize,
                         SMEM_FLOATS * 4);

    // 1) qkv = x @ w_attn + b_attn   (split-K=4 -> 768 CTAs, single wave)
    bias_init_kernel<<<(M_*QKV_N/4 + 255)/256, 256>>>(qkv, b_attn, M_, QKV_N);
    sgemm_atomic<<<dim3(QKV_N/64, M_/64, 4), 256>>>(x, w_attn, qkv, M_, QKV_N, C_, C_/4);

    // 2) attention (tf32 mma) -> g_y
    attn_kernel<<<B_*H_, 256, SMEM_FLOATS * 4>>>(k_cache, v_cache, sp, ic);

    // 3) out = y @ w_proj + b_proj   (split-K=4 -> 256 CTAs)
    bias_init_kernel<<<(M_*C_/4 + 255)/256, 256>>>(out, b_proj, M_, C_);
    sgemm_atomic<<<dim3(C_/64, M_/64, 4), 256>>>(y, w_proj, out, M_, C_, C_, C_/4);
}

// round 5
// speedup vs baseline: 1.7639x; 1.2189x over previous
#include <cuda_runtime.h>
#include <cstdint>

#define B_ 16
#define T_ 8
#define C_ 2048
#define H_ 16
#define D_ 128
#define MAXSEQ 4096
#define QKV_N (3*C_)   // 6144
#define M_ (B_*T_)     // 128

// Scratch (no allocations allowed) -------------------------------------------
__device__ float g_qkv[M_ * QKV_N];   // [b*T+t][3C]  q|k|v packed
__device__ float g_y[M_ * C_];        // attention output [b*T+t][h*D+d]

// ---------------------------------------------------------------------------
__device__ __forceinline__ float tf32f(float x) {
    uint32_t r; asm("cvt.rna.tf32.f32 %0, %1;" : "=r"(r) : "f"(x));
    return __uint_as_float(r);
}

__device__ __forceinline__ void mma_full(float* d, uint32_t a0, uint32_t a1,
                                         uint32_t a2, uint32_t a3,
                                         uint32_t b0, uint32_t b1) {
    asm volatile(
        "mma.sync.aligned.m16n8k8.row.col.f32.tf32.tf32.f32 "
        "{%0,%1,%2,%3}, {%4,%5,%6,%7}, {%8,%9}, {%0,%1,%2,%3};"
        : "+f"(d[0]), "+f"(d[1]), "+f"(d[2]), "+f"(d[3])
        : "r"(a0), "r"(a1), "r"(a2), "r"(a3), "r"(b0), "r"(b1));
}

__device__ __forceinline__ void mma8(float* d, uint32_t a0, uint32_t a2,
                                     uint32_t b0, uint32_t b1) {
    mma_full(d, a0, 0u, a2, 0u, b0, b1);
}

__device__ __forceinline__ void cpa16(uint32_t dst, const void* src, int srcsize) {
    asm volatile("cp.async.cg.shared.global [%0], [%1], 16, %2;"
                 :: "r"(dst), "l"(src), "r"(srcsize));
}
__device__ __forceinline__ void cpa_commit() {
    asm volatile("cp.async.commit_group;");
}
__device__ __forceinline__ void cpa_wait0() {
    asm volatile("cp.async.wait_group 0;");
}
__device__ __forceinline__ void cpa_wait1() {
    asm volatile("cp.async.wait_group 1;");
}

// ---------------------------------------------------------------------------
// One launch initializes qkv (b_attn) and out (b_proj).
#define QKV_Q4 (M_*QKV_N/4)   // 196608
#define OUT_Q4 (M_*C_/4)      // 65536
__global__ void bias_init2(float* __restrict__ qkv, const float* __restrict__ battn,
                           float* __restrict__ out, const float* __restrict__ bproj) {
    int i = blockIdx.x * blockDim.x + threadIdx.x;
    if (i < QKV_Q4) {
        int n = (i << 2) % QKV_N;
        ((float4*)qkv)[i] = *(const float4*)(battn + n);
    } else if (i < QKV_Q4 + OUT_Q4) {
        int j = i - QKV_Q4;
        int n = (j << 2) % C_;
        ((float4*)out)[j] = *(const float4*)(bproj + n);
    }
}

// ---------------------------------------------------------------------------
// 3xTF32 tensor-core GEMM: C[m][n] += A[128 x K] * W[K x N] over k-slice.
// CTA tile 128x64, BK=16, 256 threads, 8 warps of m32n32. atomicAdd epilogue.
// smem: hi/lo interleaved [row][2k+{0,1}], row width GW=40 (conflict-free frags).
#define GW 40
#define GEMM_SMEM_FLOATS (2*128*GW + 2*64*GW)  // 15360 -> 61440 B

__global__ void __launch_bounds__(256, 2)
tf32_gemm(const float* __restrict__ A, const float* __restrict__ W,
          float* __restrict__ Cmat, int N, int K, int kLen) {
    extern __shared__ float sh[];
    float* As = sh;                 // [2][128][GW]
    float* Bs = sh + 2*128*GW;      // [2][64][GW]

    int tid  = threadIdx.x;
    int lane = tid & 31, w = tid >> 5;
    int g = lane >> 2, c4 = lane & 3;
    int n0 = blockIdx.x * 64;
    int k0 = blockIdx.z * kLen;
    int wm = (w & 3) * 32, wn = (w >> 2) * 32;

    int arow = tid >> 1, akg = (tid & 1) * 8;   // A loader
    int bn   = tid & 63, bkg = (tid >> 6) * 4;  // B loader

    float acc[2][4][4];
    #pragma unroll
    for (int mt = 0; mt < 2; mt++)
        #pragma unroll
        for (int nt = 0; nt < 4; nt++)
            #pragma unroll
            for (int j = 0; j < 4; j++) acc[mt][nt][j] = 0.f;

    float4 ra0, ra1;
    float  rb[4];
    int iters = kLen >> 4;

    // prefetch iter 0
    {
        const float* pa = A + (size_t)arow * K + k0 + akg;
        ra0 = *(const float4*)pa; ra1 = *(const float4*)(pa + 4);
        #pragma unroll
        for (int j = 0; j < 4; j++)
            rb[j] = W[(size_t)(k0 + bkg + j) * N + n0 + bn];
    }
    // convert + store stage 0
    {
        float v[8] = {ra0.x, ra0.y, ra0.z, ra0.w, ra1.x, ra1.y, ra1.z, ra1.w};
        float* ap = As + arow * GW + 2 * akg;
        #pragma unroll
        for (int j = 0; j < 4; j++) {
            float h0 = tf32f(v[2*j]),   l0 = tf32f(v[2*j]   - h0);
            float h1 = tf32f(v[2*j+1]), l1 = tf32f(v[2*j+1] - h1);
            *(float4*)(ap + 4*j) = make_float4(h0, l0, h1, l1);
        }
        float* bp = Bs + bn * GW + 2 * bkg;
        #pragma unroll
        for (int j = 0; j < 4; j++) {
            float h = tf32f(rb[j]), l = tf32f(rb[j] - h);
            *(float2*)(bp + 2*j) = make_float2(h, l);
        }
    }
    __syncthreads();

    for (int it = 0; it < iters; it++) {
        if (it + 1 < iters) {
            const float* pa = A + (size_t)arow * K + k0 + (it+1)*16 + akg;
            ra0 = *(const float4*)pa; ra1 = *(const float4*)(pa + 4);
            #pragma unroll
            for (int j = 0; j < 4; j++)
                rb[j] = W[(size_t)(k0 + (it+1)*16 + bkg + j) * N + n0 + bn];
        }
        // compute on stage it&1
        {
            const float* as = As + (it & 1) * 128 * GW;
            const float* bs = Bs + (it & 1) * 64 * GW;
            #pragma unroll
            for (int k8 = 0; k8 < 2; k8++) {
                float2 ap[2][4];
                #pragma unroll
                for (int mt = 0; mt < 2; mt++) {
                    const float* b0 = as + (size_t)(wm + mt*16 + g) * GW + 16*k8 + 2*c4;
                    const float* b1 = as + (size_t)(wm + mt*16 + 8 + g) * GW + 16*k8 + 2*c4;
                    ap[mt][0] = *(const float2*)(b0);
                    ap[mt][1] = *(const float2*)(b1);
                    ap[mt][2] = *(const float2*)(b0 + 8);
                    ap[mt][3] = *(const float2*)(b1 + 8);
                }
                #pragma unroll
                for (int nt = 0; nt < 4; nt++) {
                    const float* bb = bs + (size_t)(wn + nt*8 + g) * GW + 16*k8 + 2*c4;
                    float2 b0p = *(const float2*)(bb);
                    float2 b1p = *(const float2*)(bb + 8);
                    uint32_t b0h = __float_as_uint(b0p.x), b0l = __float_as_uint(b0p.y);
                    uint32_t b1h = __float_as_uint(b1p.x), b1l = __float_as_uint(b1p.y);
                    #pragma unroll
                    for (int mt = 0; mt < 2; mt++) {
                        uint32_t a0h = __float_as_uint(ap[mt][0].x), a0l = __float_as_uint(ap[mt][0].y);
                        uint32_t a1h = __float_as_uint(ap[mt][1].x), a1l = __float_as_uint(ap[mt][1].y);
                        uint32_t a2h = __float_as_uint(ap[mt][2].x), a2l = __float_as_uint(ap[mt][2].y);
                        uint32_t a3h = __float_as_uint(ap[mt][3].x), a3l = __float_as_uint(ap[mt][3].y);
                        mma_full(acc[mt][nt], a0h, a1h, a2h, a3h, b0h, b1h);
                        mma_full(acc[mt][nt], a0h, a1h, a2h, a3h, b0l, b1l);
                        mma_full(acc[mt][nt], a0l, a1l, a2l, a3l, b0h, b1h);
                    }
                }
            }
        }
        if (it + 1 < iters) {
            int st = (it + 1) & 1;
            float v[8] = {ra0.x, ra0.y, ra0.z, ra0.w, ra1.x, ra1.y, ra1.z, ra1.w};
            float* apx = As + st * 128 * GW + arow * GW + 2 * akg;
            #pragma unroll
            for (int j = 0; j < 4; j++) {
                float h0 = tf32f(v[2*j]),   l0 = tf32f(v[2*j]   - h0);
                float h1 = tf32f(v[2*j+1]), l1 = tf32f(v[2*j+1] - h1);
                *(float4*)(apx + 4*j) = make_float4(h0, l0, h1, l1);
            }
            float* bpx = Bs + st * 64 * GW + bn * GW + 2 * bkg;
            #pragma unroll
            for (int j = 0; j < 4; j++) {
                float h = tf32f(rb[j]), l = tf32f(rb[j] - h);
                *(float2*)(bpx + 2*j) = make_float2(h, l);
            }
        }
        __syncthreads();
    }

    #pragma unroll
    for (int mt = 0; mt < 2; mt++)
        #pragma unroll
        for (int nt = 0; nt < 4; nt++) {
            int m   = wm + mt*16 + g;
            int col = n0 + wn + nt*8 + 2*c4;
            atomicAdd(&Cmat[(size_t)m * N + col],       acc[mt][nt][0]);
            atomicAdd(&Cmat[(size_t)m * N + col + 1],   acc[mt][nt][1]);
            atomicAdd(&Cmat[(size_t)(m+8) * N + col],   acc[mt][nt][2]);
            atomicAdd(&Cmat[(size_t)(m+8) * N + col+1], acc[mt][nt][3]);
        }
}

// ---------------------------------------------------------------------------
// Flash attention, tf32 mma, TILE_S=64, cp.async double-buffered K/V streams.
// One CTA per (b,h), 8 warps. Warp w: 8 s-cols (scores) / 16 d-cols (PV).
#define TILE 64
#define TS 132
#define PS 68
#define ASM_FLOATS (16*TS + 2*TILE*TS + 16*PS + 24)   // 20120 floats ~ 79 KB

__global__ void __launch_bounds__(256, 2)
attn_kernel(const float* __restrict__ k_cache,
            const float* __restrict__ v_cache,
            const int* __restrict__ sp_ptr,
            const int* __restrict__ causal_ptr) {
    extern __shared__ float sm[];
    float* q    = sm;                   // 16 x TS (rows 8-15 zero)
    float* Kbuf = sm + 16*TS;           // TILE x TS
    float* Vbuf = Kbuf + TILE*TS;       // TILE x TS
    float* p    = Vbuf + TILE*TS;       // 16 x PS (rows 8-15 zero)
    float* mbuf = p + 16*PS;
    float* lbuf = mbuf + 8;
    float* cbuf = lbuf + 8;

    uint32_t Ku = (uint32_t)__cvta_generic_to_shared(Kbuf);
    uint32_t Vu = (uint32_t)__cvta_generic_to_shared(Vbuf);

    int tid  = threadIdx.x;
    int lane = tid & 31;
    int w    = tid >> 5;
    int b = blockIdx.x >> 4, h = blockIdx.x & 15;
    int sp = *sp_ptr;
    int causal = *causal_ptr;
    int S = sp + T_;
    int g = lane >> 2, c4 = lane & 3;

    const float* kc = k_cache + (size_t)(b*H_ + h) * MAXSEQ * D_;
    const float* vc = v_cache + (size_t)(b*H_ + h) * MAXSEQ * D_;
    const float* kf = g_qkv + (size_t)b * T_ * QKV_N + C_   + h*D_;
    const float* vf = g_qkv + (size_t)b * T_ * QKV_N + 2*C_ + h*D_;

    for (int i = tid; i < 16*TS; i += 256) q[i] = 0.f;
    for (int i = tid; i < 16*PS; i += 256) p[i] = 0.f;
    if (tid < 8) { mbuf[tid] = -1e30f; lbuf[tid] = 0.f; }
    __syncthreads();
    {
        int t = tid >> 5;
        int d = lane * 4;
        float4 v4 = *(const float4*)(g_qkv + (size_t)(b*T_ + t)*QKV_N + h*D_ + d);
        const float sc = 0.08838834764831845f;   // 1/sqrt(128)
        q[t*TS + d + 0] = tf32f(v4.x * sc);
        q[t*TS + d + 1] = tf32f(v4.y * sc);
        q[t*TS + d + 2] = tf32f(v4.z * sc);
        q[t*TS + d + 3] = tf32f(v4.w * sc);
    }

    float oacc[2][4];
    #pragma unroll
    for (int nt = 0; nt < 2; nt++)
        #pragma unroll
        for (int j = 0; j < 4; j++) oacc[nt][j] = 0.f;

    int ntiles = (S + TILE - 1) / TILE;

    // issue K tile 0
    #pragma unroll
    for (int j = 0; j < 8; j++) {
        int c = tid + j*256;
        int r = c >> 5, col = c & 31;
        int s = r;                                // s0 = 0
        const float* src; int sz;
        if (s < sp)     { src = kc + (size_t)s*D_ + col*4; sz = 16; }
        else if (s < S) { src = kf + (size_t)(s - sp)*QKV_N + col*4; sz = 16; }
        else            { src = kc + col*4; sz = 0; }
        cpa16(Ku + (uint32_t)(r*TS + col*4)*4u, src, sz);
    }
    cpa_commit();
    cpa_wait0();
    __syncthreads();

    for (int ti = 0; ti < ntiles; ti++) {
        int s0 = ti * TILE;
        // issue V tile ti
        #pragma unroll
        for (int j = 0; j < 8; j++) {
            int c = tid + j*256;
            int r = c >> 5, col = c & 31;
            int s = s0 + r;
            const float* src; int sz;
            if (s < sp)     { src = vc + (size_t)s*D_ + col*4; sz = 16; }
            else if (s < S) { src = vf + (size_t)(s - sp)*QKV_N + col*4; sz = 16; }
            else            { src = vc + col*4; sz = 0; }
            cpa16(Vu + (uint32_t)(r*TS + col*4)*4u, src, sz);
        }
        cpa_commit();

        // ---- scores on Kbuf: warp w -> s-cols [8w, 8w+8) ----
        {
            float sc2[4] = {0.f, 0.f, 0.f, 0.f};
            #pragma unroll
            for (int ks = 0; ks < 16; ks++) {
                uint32_t a0 = __float_as_uint(q[g*TS + 8*ks + c4]);
                uint32_t a2 = __float_as_uint(q[g*TS + 8*ks + c4 + 4]);
                const float* kb = Kbuf + (size_t)(8*w + g)*TS + 8*ks + c4;
                mma8(sc2, a0, a2, __float_as_uint(kb[0]), __float_as_uint(kb[4]));
            }
            *(float2*)(p + g*PS + 8*w + 2*c4) = make_float2(sc2[0], sc2[1]);
        }
        __syncthreads();

        // ---- online softmax: warp w owns row t=w (64 cols, 2/lane) ----
        {
            int t = w;
            float v0 = p[t*PS + lane];
            float v1 = p[t*PS + lane + 32];
            int sg0 = s0 + lane, sg1 = s0 + lane + 32;
            bool ok0 = (sg0 < S) && (!causal || sg0 <= t);
            bool ok1 = (sg1 < S) && (!causal || sg1 <= t);
            v0 = ok0 ? v0 : -1e30f;
            v1 = ok1 ? v1 : -1e30f;
            float mx = fmaxf(v0, v1);
            #pragma unroll
            for (int o = 16; o > 0; o >>= 1)
                mx = fmaxf(mx, __shfl_xor_sync(0xffffffffu, mx, o));
            float mold = mbuf[t];
            float mnew = fmaxf(mold, mx);
            float e0 = ok0 ? tf32f(__expf(v0 - mnew)) : 0.f;
            float e1 = ok1 ? tf32f(__expf(v1 - mnew)) : 0.f;
            p[t*PS + lane]      = e0;
            p[t*PS + lane + 32] = e1;
            float sum = e0 + e1;
            #pragma unroll
            for (int o = 16; o > 0; o >>= 1)
                sum += __shfl_xor_sync(0xffffffffu, sum, o);
            if (lane == 0) {
                float cc = __expf(mold - mnew);
                cbuf[t] = cc;
                lbuf[t] = lbuf[t] * cc + sum;
                mbuf[t] = mnew;
            }
        }
        __syncthreads();

        // issue K tile ti+1 (overwrites Kbuf; all score reads done)
        if (ti + 1 < ntiles) {
            int s0n = s0 + TILE;
            #pragma unroll
            for (int j = 0; j < 8; j++) {
                int c = tid + j*256;
                int r = c >> 5, col = c & 31;
                int s = s0n + r;
                const float* src; int sz;
                if (s < sp)     { src = kc + (size_t)s*D_ + col*4; sz = 16; }
                else if (s < S) { src = kf + (size_t)(s - sp)*QKV_N + col*4; sz = 16; }
                else            { src = kc + col*4; sz = 0; }
                cpa16(Ku + (uint32_t)(r*TS + col*4)*4u, src, sz);
            }
            cpa_commit();
            cpa_wait1();          // V_ti arrived (K_{ti+1} still pending)
        } else {
            cpa_wait0();          // V_ti arrived
        }
        __syncthreads();

        // ---- rescale O fragments ----
        {
            float cf = cbuf[g];
            #pragma unroll
            for (int nt = 0; nt < 2; nt++) { oacc[nt][0] *= cf; oacc[nt][1] *= cf; }
        }

        // ---- PV on Vbuf: warp w -> d-cols [16w, 16w+16) ----
        #pragma unroll
        for (int ks = 0; ks < 8; ks++) {
            uint32_t a0 = __float_as_uint(p[g*PS + 8*ks + c4]);
            uint32_t a2 = __float_as_uint(p[g*PS + 8*ks + c4 + 4]);
            #pragma unroll
            for (int nt = 0; nt < 2; nt++) {
                int n0 = 16*w + 8*nt;
                uint32_t b0 = __float_as_uint(Vbuf[(size_t)(8*ks + c4)*TS + n0 + g]);
                uint32_t b1 = __float_as_uint(Vbuf[(size_t)(8*ks + c4 + 4)*TS + n0 + g]);
                mma8(oacc[nt], a0, a2, b0, b1);
            }
        }
        if (ti + 1 < ntiles) cpa_wait0();    // K_{ti+1} arrived
        __syncthreads();                      // PV reads done; K visible
    }

    // ---- epilogue: normalize, direct store ----
    {
        float l = lbuf[g];
        float inv = (l > 0.f) ? (1.f / l) : 0.f;
        #pragma unroll
        for (int nt = 0; nt < 2; nt++) {
            int d0 = 16*w + 8*nt + 2*c4;
            float2 o = make_float2(oacc[nt][0]*inv, oacc[nt][1]*inv);
            *(float2*)(g_y + (size_t)(b*T_ + g)*C_ + h*D_ + d0) = o;
        }
    }
}

// ---------------------------------------------------------------------------
extern "C" void kernel_launch(void* const* d_in, const int* in_sizes, int n_in,
                              void* d_out, int out_size) {
    const float* x       = (const float*)d_in[0];
    const float* k_cache = (const float*)d_in[1];
    const float* v_cache = (const float*)d_in[2];
    const float* w_attn  = (const float*)d_in[3];
    const float* b_attn  = (const float*)d_in[4];
    const float* w_proj  = (const float*)d_in[5];
    const float* b_proj  = (const float*)d_in[6];
    const int*   sp      = (const int*)d_in[7];
    const int*   ic      = (const int*)d_in[8];
    float* out = (float*)d_out;

    float *qkv, *y;
    cudaGetSymbolAddress((void**)&qkv, g_qkv);
    cudaGetSymbolAddress((void**)&y, g_y);

    cudaFuncSetAttribute(tf32_gemm, cudaFuncAttributeMaxDynamicSharedMemorySize,
                         GEMM_SMEM_FLOATS * 4);
    cudaFuncSetAttribute(attn_kernel, cudaFuncAttributeMaxDynamicSharedMemorySize,
                         ASM_FLOATS * 4);

    // 0) both bias inits in one launch
    bias_init2<<<(QKV_Q4 + OUT_Q4 + 255)/256, 256>>>(qkv, b_attn, out, b_proj);

    // 1) qkv += x @ w_attn   (3xTF32 tensor cores, split-K=4 -> 384 CTAs)
    tf32_gemm<<<dim3(QKV_N/64, 1, 4), 256, GEMM_SMEM_FLOATS*4>>>(
        x, w_attn, qkv, QKV_N, C_, C_/4);

    // 2) attention (tf32 mma + cp.async pipeline) -> g_y
    attn_kernel<<<B_*H_, 256, ASM_FLOATS*4>>>(k_cache, v_cache, sp, ic);

    // 3) out += y @ w_proj   (split-K=8 -> 256 CTAs)
    tf32_gemm<<<dim3(C_/64, 1, 8), 256, GEMM_SMEM_FLOATS*4>>>(
        y, w_proj, out, C_, C_, C_/8);
}

// round 7
// speedup vs baseline: 2.9051x; 1.6470x over previous
#include <cuda_runtime.h>
#include <cstdint>

#define B_ 16
#define T_ 8
#define C_ 2048
#define H_ 16
#define D_ 128
#define MAXSEQ 4096
#define QKV_N (3*C_)   // 6144
#define M_ (B_*T_)     // 128
#define SPLITS 8

// Scratch (no allocations allowed) -------------------------------------------
__device__ float  g_qkv[M_ * QKV_N];               // [b*T+t][3C]  q|k|v
__device__ float  g_y[M_ * C_];                    // attention output
__device__ float  g_part[B_*H_*SPLITS * 8 * 128];  // unnormalized O per split
__device__ float2 g_ml[B_*H_*SPLITS * 8];          // (m,l) per split per t

// ---------------------------------------------------------------------------
__device__ __forceinline__ float tf32f(float x) {
    uint32_t r; asm("cvt.rna.tf32.f32 %0, %1;" : "=r"(r) : "f"(x));
    return __uint_as_float(r);
}
__device__ __forceinline__ void mma_full(float* d, uint32_t a0, uint32_t a1,
                                         uint32_t a2, uint32_t a3,
                                         uint32_t b0, uint32_t b1) {
    asm volatile(
        "mma.sync.aligned.m16n8k8.row.col.f32.tf32.tf32.f32 "
        "{%0,%1,%2,%3}, {%4,%5,%6,%7}, {%8,%9}, {%0,%1,%2,%3};"
        : "+f"(d[0]), "+f"(d[1]), "+f"(d[2]), "+f"(d[3])
        : "r"(a0), "r"(a1), "r"(a2), "r"(a3), "r"(b0), "r"(b1));
}
__device__ __forceinline__ void mma8(float* d, uint32_t a0, uint32_t a2,
                                     uint32_t b0, uint32_t b1) {
    mma_full(d, a0, 0u, a2, 0u, b0, b1);
}
__device__ __forceinline__ void cpa16(uint32_t dst, const void* src, int srcsize) {
    asm volatile("cp.async.cg.shared.global [%0], [%1], 16, %2;"
                 :: "r"(dst), "l"(src), "r"(srcsize) : "memory");
}
__device__ __forceinline__ void cpa_commit() {
    asm volatile("cp.async.commit_group;" ::: "memory");
}
__device__ __forceinline__ void cpa_wait0() {
    asm volatile("cp.async.wait_group 0;" ::: "memory");
}
__device__ __forceinline__ void cpa_wait1() {
    asm volatile("cp.async.wait_group 1;" ::: "memory");
}

// ---------------------------------------------------------------------------
#define QKV_Q4 (M_*QKV_N/4)
#define OUT_Q4 (M_*C_/4)
__global__ void bias_init2(float* __restrict__ qkv, const float* __restrict__ battn,
                           float* __restrict__ out, const float* __restrict__ bproj) {
    int i = blockIdx.x * blockDim.x + threadIdx.x;
    if (i < QKV_Q4) {
        int n = (i << 2) % QKV_N;
        ((float4*)qkv)[i] = *(const float4*)(battn + n);
    } else if (i < QKV_Q4 + OUT_Q4) {
        int j = i - QKV_Q4;
        int n = (j << 2) % C_;
        ((float4*)out)[j] = *(const float4*)(bproj + n);
    }
}

// ---------------------------------------------------------------------------
// 3xTF32 tensor-core GEMM: C[m][n] += A[128 x K] * W[K x N] over k-slice.
// CTA tile 128x64, BK=16, 256 threads, 8 warps m32n32, atomicAdd epilogue.
#define GW 40
#define GEMM_SMEM_FLOATS (2*128*GW + 2*64*GW)   // 61440 B

__global__ void __launch_bounds__(256, 2)
tf32_gemm(const float* __restrict__ A, const float* __restrict__ W,
          float* __restrict__ Cmat, int N, int K, int kLen) {
    extern __shared__ float sh[];
    float* As = sh;                 // [2][128][GW]
    float* Bs = sh + 2*128*GW;      // [2][64][GW]

    int tid  = threadIdx.x;
    int lane = tid & 31, w = tid >> 5;
    int g = lane >> 2, c4 = lane & 3;
    int n0 = blockIdx.x * 64;
    int k0 = blockIdx.z * kLen;
    int iters = (min(kLen, K - k0)) >> 4;
    int wm = (w & 3) * 32, wn = (w >> 2) * 32;

    int arow = tid >> 1, akg = (tid & 1) * 8;
    int bn   = tid & 63, bkg = (tid >> 6) * 4;

    float acc[2][4][4];
    #pragma unroll
    for (int mt = 0; mt < 2; mt++)
        #pragma unroll
        for (int nt = 0; nt < 4; nt++)
            #pragma unroll
            for (int j = 0; j < 4; j++) acc[mt][nt][j] = 0.f;

    float4 ra0, ra1;
    float  rb[4];

    {
        const float* pa = A + (size_t)arow * K + k0 + akg;
        ra0 = *(const float4*)pa; ra1 = *(const float4*)(pa + 4);
        #pragma unroll
        for (int j = 0; j < 4; j++)
            rb[j] = W[(size_t)(k0 + bkg + j) * N + n0 + bn];
    }
    {
        float v[8] = {ra0.x, ra0.y, ra0.z, ra0.w, ra1.x, ra1.y, ra1.z, ra1.w};
        float* ap = As + arow * GW + 2 * akg;
        #pragma unroll
        for (int j = 0; j < 4; j++) {
            float h0 = tf32f(v[2*j]),   l0 = tf32f(v[2*j]   - h0);
            float h1 = tf32f(v[2*j+1]), l1 = tf32f(v[2*j+1] - h1);
            *(float4*)(ap + 4*j) = make_float4(h0, l0, h1, l1);
        }
        float* bp = Bs + bn * GW + 2 * bkg;
        #pragma unroll
        for (int j = 0; j < 4; j++) {
            float h = tf32f(rb[j]), l = tf32f(rb[j] - h);
            *(float2*)(bp + 2*j) = make_float2(h, l);
        }
    }
    __syncthreads();

    for (int it = 0; it < iters; it++) {
        if (it + 1 < iters) {
            const float* pa = A + (size_t)arow * K + k0 + (it+1)*16 + akg;
            ra0 = *(const float4*)pa; ra1 = *(const float4*)(pa + 4);
            #pragma unroll
            for (int j = 0; j < 4; j++)
                rb[j] = W[(size_t)(k0 + (it+1)*16 + bkg + j) * N + n0 + bn];
        }
        {
            const float* as = As + (it & 1) * 128 * GW;
            const float* bs = Bs + (it & 1) * 64 * GW;
            #pragma unroll
            for (int k8 = 0; k8 < 2; k8++) {
                float2 af[2][4];
                #pragma unroll
                for (int mt = 0; mt < 2; mt++) {
                    const float* b0 = as + (size_t)(wm + mt*16 + g) * GW + 16*k8 + 2*c4;
                    const float* b1 = as + (size_t)(wm + mt*16 + 8 + g) * GW + 16*k8 + 2*c4;
                    af[mt][0] = *(const float2*)(b0);
                    af[mt][1] = *(const float2*)(b1);
                    af[mt][2] = *(const float2*)(b0 + 8);
                    af[mt][3] = *(const float2*)(b1 + 8);
                }
                #pragma unroll
                for (int nt = 0; nt < 4; nt++) {
                    const float* bb = bs + (size_t)(wn + nt*8 + g) * GW + 16*k8 + 2*c4;
                    float2 b0p = *(const float2*)(bb);
                    float2 b1p = *(const float2*)(bb + 8);
                    uint32_t b0h = __float_as_uint(b0p.x), b0l = __float_as_uint(b0p.y);
                    uint32_t b1h = __float_as_uint(b1p.x), b1l = __float_as_uint(b1p.y);
                    #pragma unroll
                    for (int mt = 0; mt < 2; mt++) {
                        uint32_t a0h = __float_as_uint(af[mt][0].x), a0l = __float_as_uint(af[mt][0].y);
                        uint32_t a1h = __float_as_uint(af[mt][1].x), a1l = __float_as_uint(af[mt][1].y);
                        uint32_t a2h = __float_as_uint(af[mt][2].x), a2l = __float_as_uint(af[mt][2].y);
                        uint32_t a3h = __float_as_uint(af[mt][3].x), a3l = __float_as_uint(af[mt][3].y);
                        mma_full(acc[mt][nt], a0h, a1h, a2h, a3h, b0h, b1h);
                        mma_full(acc[mt][nt], a0h, a1h, a2h, a3h, b0l, b1l);
                        mma_full(acc[mt][nt], a0l, a1l, a2l, a3l, b0h, b1h);
                    }
                }
            }
        }
        if (it + 1 < iters) {
            int st = (it + 1) & 1;
            float v[8] = {ra0.x, ra0.y, ra0.z, ra0.w, ra1.x, ra1.y, ra1.z, ra1.w};
            float* apx = As + st * 128 * GW + arow * GW + 2 * akg;
            #pragma unroll
            for (int j = 0; j < 4; j++) {
                float h0 = tf32f(v[2*j]),   l0 = tf32f(v[2*j]   - h0);
                float h1 = tf32f(v[2*j+1]), l1 = tf32f(v[2*j+1] - h1);
                *(float4*)(apx + 4*j) = make_float4(h0, l0, h1, l1);
            }
            float* bpx = Bs + st * 64 * GW + bn * GW + 2 * bkg;
            #pragma unroll
            for (int j = 0; j < 4; j++) {
                float h = tf32f(rb[j]), l = tf32f(rb[j] - h);
                *(float2*)(bpx + 2*j) = make_float2(h, l);
            }
        }
        __syncthreads();
    }

    #pragma unroll
    for (int mt = 0; mt < 2; mt++)
        #pragma unroll
        for (int nt = 0; nt < 4; nt++) {
            int m   = wm + mt*16 + g;
            int col = n0 + wn + nt*8 + 2*c4;
            atomicAdd(&Cmat[(size_t)m * N + col],       acc[mt][nt][0]);
            atomicAdd(&Cmat[(size_t)m * N + col + 1],   acc[mt][nt][1]);
            atomicAdd(&Cmat[(size_t)(m+8) * N + col],   acc[mt][nt][2]);
            atomicAdd(&Cmat[(size_t)(m+8) * N + col+1], acc[mt][nt][3]);
        }
}

// ---------------------------------------------------------------------------
// Flash attention, split-S(8), tf32 mma, TILE=64, cp.async double-buffered.
// Grid = B*H*SPLITS. 8 warps; warp w: 8 s-cols (scores) / 16 d-cols (PV).
// Writes unnormalized O + (m,l) per split; attn_merge combines.
#define TILE 64
#define TS 132
#define PS 68
#define ASM_FLOATS (8*TS + 2*TILE*TS + 8*PS + 24)   // 18520 floats = 74080 B

__global__ void __launch_bounds__(256, 3)
attn_kernel(const float* __restrict__ k_cache,
            const float* __restrict__ v_cache,
            const int* __restrict__ sp_ptr,
            const int* __restrict__ causal_ptr) {
    extern __shared__ float sm[];
    float* q    = sm;                   // 8 x TS
    float* Kbuf = sm + 8*TS;            // TILE x TS
    float* Vbuf = Kbuf + TILE*TS;       // TILE x TS
    float* p    = Vbuf + TILE*TS;       // 8 x PS
    float* mbuf = p + 8*PS;
    float* lbuf = mbuf + 8;
    float* cbuf = lbuf + 8;

    uint32_t Ku = (uint32_t)__cvta_generic_to_shared(Kbuf);
    uint32_t Vu = (uint32_t)__cvta_generic_to_shared(Vbuf);

    int tid  = threadIdx.x;
    int lane = tid & 31;
    int w    = tid >> 5;
    int bh    = blockIdx.x >> 3;
    int split = blockIdx.x & 7;
    int b = bh >> 4, h = bh & 15;
    int sp = *sp_ptr;
    int causal = *causal_ptr;
    int S = sp + T_;
    int SLEN = (S + SPLITS - 1) / SPLITS;
    int sb = split * SLEN;
    int se = min(S, sb + SLEN);
    int ntiles = (se > sb) ? (se - sb + TILE - 1) / TILE : 0;
    int g = lane >> 2, c4 = lane & 3;

    const float* kc = k_cache + (size_t)bh * MAXSEQ * D_;
    const float* vc = v_cache + (size_t)bh * MAXSEQ * D_;
    const float* kf = g_qkv + (size_t)b * T_ * QKV_N + C_   + h*D_;
    const float* vf = g_qkv + (size_t)b * T_ * QKV_N + 2*C_ + h*D_;

    if (tid < 8) { mbuf[tid] = -1e30f; lbuf[tid] = 0.f; }
    {
        int t = tid >> 5;
        int d = lane * 4;
        float4 v4 = *(const float4*)(g_qkv + (size_t)(b*T_ + t)*QKV_N + h*D_ + d);
        const float sc = 0.08838834764831845f;   // 1/sqrt(128)
        q[t*TS + d + 0] = tf32f(v4.x * sc);
        q[t*TS + d + 1] = tf32f(v4.y * sc);
        q[t*TS + d + 2] = tf32f(v4.z * sc);
        q[t*TS + d + 3] = tf32f(v4.w * sc);
    }

    float oacc[2][4];
    #pragma unroll
    for (int nt = 0; nt < 2; nt++)
        #pragma unroll
        for (int j = 0; j < 4; j++) oacc[nt][j] = 0.f;

    // prologue: K tile 0 of this split
    if (ntiles > 0) {
        #pragma unroll
        for (int j = 0; j < 8; j++) {
            int c = tid + j*256;
            int r = c >> 5, col = c & 31;
            int s = sb + r;
            const float* src; int sz;
            if (s < sp && s < se) { src = kc + (size_t)s*D_ + col*4; sz = 16; }
            else if (s < se)      { src = kf + (size_t)(s - sp)*QKV_N + col*4; sz = 16; }
            else                  { src = kc; sz = 0; }
            cpa16(Ku + (uint32_t)(r*TS + col*4)*4u, src, sz);
        }
        cpa_commit();
        cpa_wait0();
    }
    __syncthreads();

    for (int ti = 0; ti < ntiles; ti++) {
        int s0 = sb + ti * TILE;
        // issue V tile ti
        #pragma unroll
        for (int j = 0; j < 8; j++) {
            int c = tid + j*256;
            int r = c >> 5, col = c & 31;
            int s = s0 + r;
            const float* src; int sz;
            if (s < sp && s < se) { src = vc + (size_t)s*D_ + col*4; sz = 16; }
            else if (s < se)      { src = vf + (size_t)(s - sp)*QKV_N + col*4; sz = 16; }
            else                  { src = vc; sz = 0; }
            cpa16(Vu + (uint32_t)(r*TS + col*4)*4u, src, sz);
        }
        cpa_commit();

        // ---- scores on Kbuf: warp w -> s-cols [8w, 8w+8) ----
        {
            float sc2[4] = {0.f, 0.f, 0.f, 0.f};
            #pragma unroll
            for (int ks = 0; ks < 16; ks++) {
                uint32_t a0 = __float_as_uint(q[g*TS + 8*ks + c4]);
                uint32_t a2 = __float_as_uint(q[g*TS + 8*ks + c4 + 4]);
                const float* kb = Kbuf + (size_t)(8*w + g)*TS + 8*ks + c4;
                mma8(sc2, a0, a2, __float_as_uint(kb[0]), __float_as_uint(kb[4]));
            }
            *(float2*)(p + g*PS + 8*w + 2*c4) = make_float2(sc2[0], sc2[1]);
        }
        __syncthreads();                         // scores done; Kbuf reusable

        // issue K tile ti+1 (while softmax runs)
        bool more = (ti + 1 < ntiles);
        if (more) {
            int s0n = s0 + TILE;
            #pragma unroll
            for (int j = 0; j < 8; j++) {
                int c = tid + j*256;
                int r = c >> 5, col = c & 31;
                int s = s0n + r;
                const float* src; int sz;
                if (s < sp && s < se) { src = kc + (size_t)s*D_ + col*4; sz = 16; }
                else if (s < se)      { src = kf + (size_t)(s - sp)*QKV_N + col*4; sz = 16; }
                else                  { src = kc; sz = 0; }
                cpa16(Ku + (uint32_t)(r*TS + col*4)*4u, src, sz);
            }
            cpa_commit();
        }

        // ---- online softmax: warp w owns row t=w ----
        {
            int t = w;
            float v0 = p[t*PS + lane];
            float v1 = p[t*PS + lane + 32];
            int sg0 = s0 + lane, sg1 = s0 + lane + 32;
            bool ok0 = (sg0 < se) && (!causal || sg0 <= t);
            bool ok1 = (sg1 < se) && (!causal || sg1 <= t);
            v0 = ok0 ? v0 : -1e30f;
            v1 = ok1 ? v1 : -1e30f;
            float mx = fmaxf(v0, v1);
            #pragma unroll
            for (int o = 16; o > 0; o >>= 1)
                mx = fmaxf(mx, __shfl_xor_sync(0xffffffffu, mx, o));
            float mold = mbuf[t];
            float mnew = fmaxf(mold, mx);
            float e0 = ok0 ? tf32f(__expf(v0 - mnew)) : 0.f;
            float e1 = ok1 ? tf32f(__expf(v1 - mnew)) : 0.f;
            p[t*PS + lane]      = e0;
            p[t*PS + lane + 32] = e1;
            float sum = e0 + e1;
            #pragma unroll
            for (int o = 16; o > 0; o >>= 1)
                sum += __shfl_xor_sync(0xffffffffu, sum, o);
            if (lane == 0) {
                float cc = __expf(mold - mnew);
                cbuf[t] = cc;
                lbuf[t] = lbuf[t] * cc + sum;
                mbuf[t] = mnew;
            }
        }
        if (more) cpa_wait1(); else cpa_wait0(); // V_ti arrived
        __syncthreads();                         // publish p rows + Vbuf

        // ---- rescale O fragments ----
        {
            float cf = cbuf[g];
            #pragma unroll
            for (int nt = 0; nt < 2; nt++) { oacc[nt][0] *= cf; oacc[nt][1] *= cf; }
        }

        // ---- PV on Vbuf: warp w -> d-cols [16w, 16w+16) ----
        #pragma unroll
        for (int ks = 0; ks < 8; ks++) {
            uint32_t a0 = __float_as_uint(p[g*PS + 8*ks + c4]);
            uint32_t a2 = __float_as_uint(p[g*PS + 8*ks + c4 + 4]);
            #pragma unroll
            for (int nt = 0; nt < 2; nt++) {
                int n0 = 16*w + 8*nt;
                uint32_t b0 = __float_as_uint(Vbuf[(size_t)(8*ks + c4)*TS + n0 + g]);
                uint32_t b1 = __float_as_uint(Vbuf[(size_t)(8*ks + c4 + 4)*TS + n0 + g]);
                mma8(oacc[nt], a0, a2, b0, b1);
            }
        }
        if (more) cpa_wait0();                   // K_{ti+1} arrived
        __syncthreads();                         // PV reads done
    }

    // ---- epilogue: unnormalized partials + (m,l) ----
    {
        float* po = g_part + (size_t)blockIdx.x * 1024;
        #pragma unroll
        for (int nt = 0; nt < 2; nt++) {
            int d0 = 16*w + 8*nt + 2*c4;
            *(float2*)(po + g*128 + d0) = make_float2(oacc[nt][0], oacc[nt][1]);
        }
        if (tid < 8)
            g_ml[(size_t)blockIdx.x * 8 + tid] = make_float2(mbuf[tid], lbuf[tid]);
    }
}

// ---------------------------------------------------------------------------
// Merge SPLITS partials -> g_y. One warp per (bh,t), lane covers 4 d.
__global__ void attn_merge() {
    int wi = blockIdx.x * 8 + (threadIdx.x >> 5);   // 0..2047 = bh*8 + t
    int lane = threadIdx.x & 31;
    int bh = wi >> 3, t = wi & 7;
    int b = bh >> 4, h = bh & 15;
    int d0 = lane * 4;

    float mstar = -1e30f;
    float2 ml[SPLITS];
    #pragma unroll
    for (int s = 0; s < SPLITS; s++) {
        ml[s] = g_ml[(size_t)(bh*SPLITS + s) * 8 + t];
        mstar = fmaxf(mstar, ml[s].x);
    }
    float lstar = 0.f;
    float4 acc = make_float4(0.f, 0.f, 0.f, 0.f);
    #pragma unroll
    for (int s = 0; s < SPLITS; s++) {
        float ws = __expf(ml[s].x - mstar);
        lstar += ws * ml[s].y;
        float4 o = *(const float4*)(g_part + (size_t)(bh*SPLITS + s)*1024 + t*128 + d0);
        acc.x += ws*o.x; acc.y += ws*o.y; acc.z += ws*o.z; acc.w += ws*o.w;
    }
    float inv = (lstar > 0.f) ? (1.f / lstar) : 0.f;
    acc.x *= inv; acc.y *= inv; acc.z *= inv; acc.w *= inv;
    *(float4*)(g_y + (size_t)(b*T_ + t)*C_ + h*D_ + d0) = acc;
}

// ---------------------------------------------------------------------------
extern "C" void kernel_launch(void* const* d_in, const int* in_sizes, int n_in,
                              void* d_out, int out_size) {
    const float* x       = (const float*)d_in[0];
    const float* k_cache = (const float*)d_in[1];
    const float* v_cache = (const float*)d_in[2];
    const float* w_attn  = (const float*)d_in[3];
    const float* b_attn  = (const float*)d_in[4];
    const float* w_proj  = (const float*)d_in[5];
    const float* b_proj  = (const float*)d_in[6];
    const int*   sp      = (const int*)d_in[7];
    const int*   ic      = (const int*)d_in[8];
    float* out = (float*)d_out;

    float *qkv, *y;
    cudaGetSymbolAddress((void**)&qkv, g_qkv);
    cudaGetSymbolAddress((void**)&y, g_y);

    cudaFuncSetAttribute(tf32_gemm, cudaFuncAttributeMaxDynamicSharedMemorySize,
                         GEMM_SMEM_FLOATS * 4);
    cudaFuncSetAttribute(attn_kernel, cudaFuncAttributeMaxDynamicSharedMemorySize,
                         ASM_FLOATS * 4);

    // 0) both bias inits
    bias_init2<<<(QKV_Q4 + OUT_Q4 + 255)/256, 256>>>(qkv, b_attn, out, b_proj);

    // 1) qkv += x @ w_attn  (96 n-blocks x split-K 3 = 288 CTAs, one wave)
    tf32_gemm<<<dim3(QKV_N/64, 1, 3), 256, GEMM_SMEM_FLOATS*4>>>(
        x, w_attn, qkv, QKV_N, C_, 688);

    // 2) attention split-S -> partials, then merge -> g_y
    attn_kernel<<<B_*H_*SPLITS, 256, ASM_FLOATS*4>>>(k_cache, v_cache, sp, ic);
    attn_merge<<<256, 256>>>();

    // 3) out += y @ w_proj  (split-K=8 -> 256 CTAs)
    tf32_gemm<<<dim3(C_/64, 1, 8), 256, GEMM_SMEM_FLOATS*4>>>(
        y, w_proj, out, C_, C_, C_/8);
}

// round 8
// speedup vs baseline: 2.9504x; 1.0156x over previous
#include <cuda_runtime.h>
#include <cstdint>

#define B_ 16
#define T_ 8
#define C_ 2048
#define H_ 16
#define D_ 128
#define MAXSEQ 4096
#define QKV_N (3*C_)   // 6144
#define M_ (B_*T_)     // 128
#define SPLITS 8

// Scratch (no allocations allowed) -------------------------------------------
__device__ float  g_qkv[M_ * QKV_N];               // [b*T+t][3C]  q|k|v
__device__ float  g_y[M_ * C_];                    // attention output
__device__ float  g_part[B_*H_*SPLITS * 8 * 128];  // unnormalized O per split
__device__ float2 g_ml[B_*H_*SPLITS * 8];          // (m,l) per split per t

// ---------------------------------------------------------------------------
__device__ __forceinline__ float tf32f(float x) {
    uint32_t r; asm("cvt.rna.tf32.f32 %0, %1;" : "=r"(r) : "f"(x));
    return __uint_as_float(r);
}
__device__ __forceinline__ void mma_full(float* d, uint32_t a0, uint32_t a1,
                                         uint32_t a2, uint32_t a3,
                                         uint32_t b0, uint32_t b1) {
    asm volatile(
        "mma.sync.aligned.m16n8k8.row.col.f32.tf32.tf32.f32 "
        "{%0,%1,%2,%3}, {%4,%5,%6,%7}, {%8,%9}, {%0,%1,%2,%3};"
        : "+f"(d[0]), "+f"(d[1]), "+f"(d[2]), "+f"(d[3])
        : "r"(a0), "r"(a1), "r"(a2), "r"(a3), "r"(b0), "r"(b1));
}
__device__ __forceinline__ void mma8(float* d, uint32_t a0, uint32_t a2,
                                     uint32_t b0, uint32_t b1) {
    mma_full(d, a0, 0u, a2, 0u, b0, b1);
}
__device__ __forceinline__ void cpa16(uint32_t dst, const void* src, int srcsize) {
    asm volatile("cp.async.cg.shared.global [%0], [%1], 16, %2;"
                 :: "r"(dst), "l"(src), "r"(srcsize) : "memory");
}
__device__ __forceinline__ void cpa_commit() {
    asm volatile("cp.async.commit_group;" ::: "memory");
}
__device__ __forceinline__ void cpa_wait0() {
    asm volatile("cp.async.wait_group 0;" ::: "memory");
}
__device__ __forceinline__ void cpa_wait1() {
    asm volatile("cp.async.wait_group 1;" ::: "memory");
}

// ---------------------------------------------------------------------------
#define QKV_Q4 (M_*QKV_N/4)
#define OUT_Q4 (M_*C_/4)
__global__ void bias_init2(float* __restrict__ qkv, const float* __restrict__ battn,
                           float* __restrict__ out, const float* __restrict__ bproj) {
    int i = blockIdx.x * blockDim.x + threadIdx.x;
    if (i < QKV_Q4) {
        int n = (i << 2) % QKV_N;
        ((float4*)qkv)[i] = *(const float4*)(battn + n);
    } else if (i < QKV_Q4 + OUT_Q4) {
        int j = i - QKV_Q4;
        int n = (j << 2) % C_;
        ((float4*)out)[j] = *(const float4*)(bproj + n);
    }
}

// ---------------------------------------------------------------------------
// 3xTF32 GEMM: C[128 x N] += A[128 x K] * W[K x N] over k-slice.
// CTA tile 128x256, BK=16, 256 threads, 8 warps (2x4) of m64n64.
// smem per stage: A [16][264] (k-row-major, hi/lo interleaved along m),
//                 B [16][520] (k-row-major, hi/lo along n). 2-way LDS floor.
#define SA 264
#define SBN 520
#define STG (16*SA + 16*SBN)             // 12544 floats per stage
#define G2SMEMF (2*STG)                  // 25088 floats = 100352 B

__global__ void __launch_bounds__(256)
tf32_gemm2(const float* __restrict__ A, const float* __restrict__ W,
           float* __restrict__ Cmat, int N, int K, int kLen) {
    extern __shared__ float sh[];

    int tid  = threadIdx.x;
    int lane = tid & 31, w = tid >> 5;
    int g = lane >> 2, c4 = lane & 3;
    int n0 = blockIdx.x * 256;
    int k0 = blockIdx.z * kLen;
    int rem = K - k0;
    int iters = ((kLen < rem) ? kLen : rem) >> 4;
    int wm = (w & 1) * 64;            // warp grid 2 (m) x 4 (n)
    int wn = (w >> 1) * 64;

    // A loader: row = tid>>1 (0..127), k-half = (tid&1)*8
    int arow = tid >> 1, ah = (tid & 1) * 8;

    float acc[4][8][4];
    #pragma unroll
    for (int mt = 0; mt < 4; mt++)
        #pragma unroll
        for (int nt = 0; nt < 8; nt++)
            #pragma unroll
            for (int j = 0; j < 4; j++) acc[mt][nt][j] = 0.f;

    float4 ra0, ra1;     // 8 A values
    float  rb[16];       // 16 B values (n = tid column)

    // ---- prefetch iter 0 ----
    {
        const float* pa = A + (size_t)arow * K + k0 + ah;
        ra0 = *(const float4*)pa; ra1 = *(const float4*)(pa + 4);
        #pragma unroll
        for (int j = 0; j < 16; j++)
            rb[j] = W[(size_t)(k0 + j) * N + n0 + tid];
    }
    // ---- convert + store stage 0 ----
    {
        float* as = sh;
        float* bs = sh + 16*SA;
        float av[8] = {ra0.x, ra0.y, ra0.z, ra0.w, ra1.x, ra1.y, ra1.z, ra1.w};
        #pragma unroll
        for (int j = 0; j < 8; j++) {
            float hv = tf32f(av[j]), lv = tf32f(av[j] - hv);
            *(float2*)(as + (ah + j)*SA + 2*arow) = make_float2(hv, lv);
        }
        #pragma unroll
        for (int j = 0; j < 16; j++) {
            float hv = tf32f(rb[j]), lv = tf32f(rb[j] - hv);
            *(float2*)(bs + j*SBN + 2*tid) = make_float2(hv, lv);
        }
    }
    __syncthreads();

    for (int it = 0; it < iters; it++) {
        if (it + 1 < iters) {
            const float* pa = A + (size_t)arow * K + k0 + (it+1)*16 + ah;
            ra0 = *(const float4*)pa; ra1 = *(const float4*)(pa + 4);
            #pragma unroll
            for (int j = 0; j < 16; j++)
                rb[j] = W[(size_t)(k0 + (it+1)*16 + j) * N + n0 + tid];
        }
        // ---- compute on stage it&1 ----
        {
            const float* as = sh + (it & 1) * STG;
            const float* bs = as + 16*SA;
            #pragma unroll
            for (int k8 = 0; k8 < 2; k8++) {
                int kr0 = k8*8 + c4, kr4 = kr0 + 4;
                float2 af[4][4];   // [mt][a0,a1,a2,a3] as (hi,lo)
                #pragma unroll
                for (int mt = 0; mt < 4; mt++) {
                    int mi = 2*(wm + 16*mt + g);
                    af[mt][0] = *(const float2*)(as + kr0*SA + mi);
                    af[mt][1] = *(const float2*)(as + kr0*SA + mi + 16);
                    af[mt][2] = *(const float2*)(as + kr4*SA + mi);
                    af[mt][3] = *(const float2*)(as + kr4*SA + mi + 16);
                }
                #pragma unroll
                for (int nt = 0; nt < 8; nt++) {
                    int ni = 2*(wn + 8*nt + g);
                    float2 b0p = *(const float2*)(bs + kr0*SBN + ni);
                    float2 b1p = *(const float2*)(bs + kr4*SBN + ni);
                    uint32_t b0h = __float_as_uint(b0p.x), b0l = __float_as_uint(b0p.y);
                    uint32_t b1h = __float_as_uint(b1p.x), b1l = __float_as_uint(b1p.y);
                    #pragma unroll
                    for (int mt = 0; mt < 4; mt++) {
                        uint32_t a0h = __float_as_uint(af[mt][0].x), a0l = __float_as_uint(af[mt][0].y);
                        uint32_t a1h = __float_as_uint(af[mt][1].x), a1l = __float_as_uint(af[mt][1].y);
                        uint32_t a2h = __float_as_uint(af[mt][2].x), a2l = __float_as_uint(af[mt][2].y);
                        uint32_t a3h = __float_as_uint(af[mt][3].x), a3l = __float_as_uint(af[mt][3].y);
                        mma_full(acc[mt][nt], a0h, a1h, a2h, a3h, b0h, b1h);
                        mma_full(acc[mt][nt], a0h, a1h, a2h, a3h, b0l, b1l);
                        mma_full(acc[mt][nt], a0l, a1l, a2l, a3l, b0h, b1h);
                    }
                }
            }
        }
        if (it + 1 < iters) {
            float* as = sh + ((it+1) & 1) * STG;
            float* bs = as + 16*SA;
            float av[8] = {ra0.x, ra0.y, ra0.z, ra0.w, ra1.x, ra1.y, ra1.z, ra1.w};
            #pragma unroll
            for (int j = 0; j < 8; j++) {
                float hv = tf32f(av[j]), lv = tf32f(av[j] - hv);
                *(float2*)(as + (ah + j)*SA + 2*arow) = make_float2(hv, lv);
            }
            #pragma unroll
            for (int j = 0; j < 16; j++) {
                float hv = tf32f(rb[j]), lv = tf32f(rb[j] - hv);
                *(float2*)(bs + j*SBN + 2*tid) = make_float2(hv, lv);
            }
        }
        __syncthreads();
    }

    // ---- epilogue: atomic accumulate ----
    #pragma unroll
    for (int mt = 0; mt < 4; mt++)
        #pragma unroll
        for (int nt = 0; nt < 8; nt++) {
            int m   = wm + 16*mt + g;
            int col = n0 + wn + 8*nt + 2*c4;
            atomicAdd(&Cmat[(size_t)m * N + col],       acc[mt][nt][0]);
            atomicAdd(&Cmat[(size_t)m * N + col + 1],   acc[mt][nt][1]);
            atomicAdd(&Cmat[(size_t)(m+8) * N + col],   acc[mt][nt][2]);
            atomicAdd(&Cmat[(size_t)(m+8) * N + col+1], acc[mt][nt][3]);
        }
}

// ---------------------------------------------------------------------------
// Flash attention, split-S(8), tf32 mma, TILE=64, cp.async double-buffered.
// (unchanged from best 294us round)
#define TILE 64
#define TS 132
#define PS 68
#define ASM_FLOATS (8*TS + 2*TILE*TS + 8*PS + 24)   // 74080 B

__global__ void __launch_bounds__(256, 3)
attn_kernel(const float* __restrict__ k_cache,
            const float* __restrict__ v_cache,
            const int* __restrict__ sp_ptr,
            const int* __restrict__ causal_ptr) {
    extern __shared__ float sm[];
    float* q    = sm;                   // 8 x TS
    float* Kbuf = sm + 8*TS;            // TILE x TS
    float* Vbuf = Kbuf + TILE*TS;       // TILE x TS
    float* p    = Vbuf + TILE*TS;       // 8 x PS
    float* mbuf = p + 8*PS;
    float* lbuf = mbuf + 8;
    float* cbuf = lbuf + 8;

    uint32_t Ku = (uint32_t)__cvta_generic_to_shared(Kbuf);
    uint32_t Vu = (uint32_t)__cvta_generic_to_shared(Vbuf);

    int tid  = threadIdx.x;
    int lane = tid & 31;
    int w    = tid >> 5;
    int bh    = blockIdx.x >> 3;
    int split = blockIdx.x & 7;
    int b = bh >> 4, h = bh & 15;
    int sp = *sp_ptr;
    int causal = *causal_ptr;
    int S = sp + T_;
    int SLEN = (S + SPLITS - 1) / SPLITS;
    int sb = split * SLEN;
    int se = min(S, sb + SLEN);
    int ntiles = (se > sb) ? (se - sb + TILE - 1) / TILE : 0;
    int g = lane >> 2, c4 = lane & 3;

    const float* kc = k_cache + (size_t)bh * MAXSEQ * D_;
    const float* vc = v_cache + (size_t)bh * MAXSEQ * D_;
    const float* kf = g_qkv + (size_t)b * T_ * QKV_N + C_   + h*D_;
    const float* vf = g_qkv + (size_t)b * T_ * QKV_N + 2*C_ + h*D_;

    if (tid < 8) { mbuf[tid] = -1e30f; lbuf[tid] = 0.f; }
    {
        int t = tid >> 5;
        int d = lane * 4;
        float4 v4 = *(const float4*)(g_qkv + (size_t)(b*T_ + t)*QKV_N + h*D_ + d);
        const float sc = 0.08838834764831845f;   // 1/sqrt(128)
        q[t*TS + d + 0] = tf32f(v4.x * sc);
        q[t*TS + d + 1] = tf32f(v4.y * sc);
        q[t*TS + d + 2] = tf32f(v4.z * sc);
        q[t*TS + d + 3] = tf32f(v4.w * sc);
    }

    float oacc[2][4];
    #pragma unroll
    for (int nt = 0; nt < 2; nt++)
        #pragma unroll
        for (int j = 0; j < 4; j++) oacc[nt][j] = 0.f;

    if (ntiles > 0) {
        #pragma unroll
        for (int j = 0; j < 8; j++) {
            int c = tid + j*256;
            int r = c >> 5, col = c & 31;
            int s = sb + r;
            const float* src; int sz;
            if (s < sp && s < se) { src = kc + (size_t)s*D_ + col*4; sz = 16; }
            else if (s < se)      { src = kf + (size_t)(s - sp)*QKV_N + col*4; sz = 16; }
            else                  { src = kc; sz = 0; }
            cpa16(Ku + (uint32_t)(r*TS + col*4)*4u, src, sz);
        }
        cpa_commit();
        cpa_wait0();
    }
    __syncthreads();

    for (int ti = 0; ti < ntiles; ti++) {
        int s0 = sb + ti * TILE;
        #pragma unroll
        for (int j = 0; j < 8; j++) {
            int c = tid + j*256;
            int r = c >> 5, col = c & 31;
            int s = s0 + r;
            const float* src; int sz;
            if (s < sp && s < se) { src = vc + (size_t)s*D_ + col*4; sz = 16; }
            else if (s < se)      { src = vf + (size_t)(s - sp)*QKV_N + col*4; sz = 16; }
            else                  { src = vc; sz = 0; }
            cpa16(Vu + (uint32_t)(r*TS + col*4)*4u, src, sz);
        }
        cpa_commit();

        {
            float sc2[4] = {0.f, 0.f, 0.f, 0.f};
            #pragma unroll
            for (int ks = 0; ks < 16; ks++) {
                uint32_t a0 = __float_as_uint(q[g*TS + 8*ks + c4]);
                uint32_t a2 = __float_as_uint(q[g*TS + 8*ks + c4 + 4]);
                const float* kb = Kbuf + (size_t)(8*w + g)*TS + 8*ks + c4;
                mma8(sc2, a0, a2, __float_as_uint(kb[0]), __float_as_uint(kb[4]));
            }
            *(float2*)(p + g*PS + 8*w + 2*c4) = make_float2(sc2[0], sc2[1]);
        }
        __syncthreads();

        bool more = (ti + 1 < ntiles);
        if (more) {
            int s0n = s0 + TILE;
            #pragma unroll
            for (int j = 0; j < 8; j++) {
                int c = tid + j*256;
                int r = c >> 5, col = c & 31;
                int s = s0n + r;
                const float* src; int sz;
                if (s < sp && s < se) { src = kc + (size_t)s*D_ + col*4; sz = 16; }
                else if (s < se)      { src = kf + (size_t)(s - sp)*QKV_N + col*4; sz = 16; }
                else                  { src = kc; sz = 0; }
                cpa16(Ku + (uint32_t)(r*TS + col*4)*4u, src, sz);
            }
            cpa_commit();
        }

        {
            int t = w;
            float v0 = p[t*PS + lane];
            float v1 = p[t*PS + lane + 32];
            int sg0 = s0 + lane, sg1 = s0 + lane + 32;
            bool ok0 = (sg0 < se) && (!causal || sg0 <= t);
            bool ok1 = (sg1 < se) && (!causal || sg1 <= t);
            v0 = ok0 ? v0 : -1e30f;
            v1 = ok1 ? v1 : -1e30f;
            float mx = fmaxf(v0, v1);
            #pragma unroll
            for (int o = 16; o > 0; o >>= 1)
                mx = fmaxf(mx, __shfl_xor_sync(0xffffffffu, mx, o));
            float mold = mbuf[t];
            float mnew = fmaxf(mold, mx);
            float e0 = ok0 ? tf32f(__expf(v0 - mnew)) : 0.f;
            float e1 = ok1 ? tf32f(__expf(v1 - mnew)) : 0.f;
            p[t*PS + lane]      = e0;
            p[t*PS + lane + 32] = e1;
            float sum = e0 + e1;
            #pragma unroll
            for (int o = 16; o > 0; o >>= 1)
                sum += __shfl_xor_sync(0xffffffffu, sum, o);
            if (lane == 0) {
                float cc = __expf(mold - mnew);
                cbuf[t] = cc;
                lbuf[t] = lbuf[t] * cc + sum;
                mbuf[t] = mnew;
            }
        }
        if (more) cpa_wait1(); else cpa_wait0();
        __syncthreads();

        {
            float cf = cbuf[g];
            #pragma unroll
            for (int nt = 0; nt < 2; nt++) { oacc[nt][0] *= cf; oacc[nt][1] *= cf; }
        }

        #pragma unroll
        for (int ks = 0; ks < 8; ks++) {
            uint32_t a0 = __float_as_uint(p[g*PS + 8*ks + c4]);
            uint32_t a2 = __float_as_uint(p[g*PS + 8*ks + c4 + 4]);
            #pragma unroll
            for (int nt = 0; nt < 2; nt++) {
                int n0 = 16*w + 8*nt;
                uint32_t b0 = __float_as_uint(Vbuf[(size_t)(8*ks + c4)*TS + n0 + g]);
                uint32_t b1 = __float_as_uint(Vbuf[(size_t)(8*ks + c4 + 4)*TS + n0 + g]);
                mma8(oacc[nt], a0, a2, b0, b1);
            }
        }
        if (more) cpa_wait0();
        __syncthreads();
    }

    {
        float* po = g_part + (size_t)blockIdx.x * 1024;
        #pragma unroll
        for (int nt = 0; nt < 2; nt++) {
            int d0 = 16*w + 8*nt + 2*c4;
            *(float2*)(po + g*128 + d0) = make_float2(oacc[nt][0], oacc[nt][1]);
        }
        if (tid < 8)
            g_ml[(size_t)blockIdx.x * 8 + tid] = make_float2(mbuf[tid], lbuf[tid]);
    }
}

// ---------------------------------------------------------------------------
__global__ void attn_merge() {
    int wi = blockIdx.x * 8 + (threadIdx.x >> 5);   // bh*8 + t
    int lane = threadIdx.x & 31;
    int bh = wi >> 3, t = wi & 7;
    int b = bh >> 4, h = bh & 15;
    int d0 = lane * 4;

    float mstar = -1e30f;
    float2 ml[SPLITS];
    #pragma unroll
    for (int s = 0; s < SPLITS; s++) {
        ml[s] = g_ml[(size_t)(bh*SPLITS + s) * 8 + t];
        mstar = fmaxf(mstar, ml[s].x);
    }
    float lstar = 0.f;
    float4 acc = make_float4(0.f, 0.f, 0.f, 0.f);
    #pragma unroll
    for (int s = 0; s < SPLITS; s++) {
        float ws = __expf(ml[s].x - mstar);
        lstar += ws * ml[s].y;
        float4 o = *(const float4*)(g_part + (size_t)(bh*SPLITS + s)*1024 + t*128 + d0);
        acc.x += ws*o.x; acc.y += ws*o.y; acc.z += ws*o.z; acc.w += ws*o.w;
    }
    float inv = (lstar > 0.f) ? (1.f / lstar) : 0.f;
    acc.x *= inv; acc.y *= inv; acc.z *= inv; acc.w *= inv;
    *(float4*)(g_y + (size_t)(b*T_ + t)*C_ + h*D_ + d0) = acc;
}

// ---------------------------------------------------------------------------
extern "C" void kernel_launch(void* const* d_in, const int* in_sizes, int n_in,
                              void* d_out, int out_size) {
    const float* x       = (const float*)d_in[0];
    const float* k_cache = (const float*)d_in[1];
    const float* v_cache = (const float*)d_in[2];
    const float* w_attn  = (const float*)d_in[3];
    const float* b_attn  = (const float*)d_in[4];
    const float* w_proj  = (const float*)d_in[5];
    const float* b_proj  = (const float*)d_in[6];
    const int*   sp      = (const int*)d_in[7];
    const int*   ic      = (const int*)d_in[8];
    float* out = (float*)d_out;

    float *qkv, *y;
    cudaGetSymbolAddress((void**)&qkv, g_qkv);
    cudaGetSymbolAddress((void**)&y, g_y);

    cudaFuncSetAttribute(tf32_gemm2, cudaFuncAttributeMaxDynamicSharedMemorySize,
                         G2SMEMF * 4);
    cudaFuncSetAttribute(attn_kernel, cudaFuncAttributeMaxDynamicSharedMemorySize,
                         ASM_FLOATS * 4);

    // 0) both bias inits
    bias_init2<<<(QKV_Q4 + OUT_Q4 + 255)/256, 256>>>(qkv, b_attn, out, b_proj);

    // 1) qkv += x @ w_attn  (24 n-blocks x split-K 6 = 144 CTAs, one 1/SM wave)
    tf32_gemm2<<<dim3(QKV_N/256, 1, 6), 256, G2SMEMF*4>>>(
        x, w_attn, qkv, QKV_N, C_, 352);

    // 2) attention split-S -> partials, then merge -> g_y
    attn_kernel<<<B_*H_*SPLITS, 256, ASM_FLOATS*4>>>(k_cache, v_cache, sp, ic);
    attn_merge<<<256, 256>>>();

    // 3) out += y @ w_proj  (8 n-blocks x split-K 12 = 96 CTAs)
    tf32_gemm2<<<dim3(C_/256, 1, 12), 256, G2SMEMF*4>>>(
        y, w_proj, out, C_, C_, 176);
}

// round 9
// speedup vs baseline: 2.9517x; 1.0004x over previous
#include <cuda_runtime.h>
#include <cstdint>

#define B_ 16
#define T_ 8
#define C_ 2048
#define H_ 16
#define D_ 128
#define MAXSEQ 4096
#define QKV_N (3*C_)   // 6144
#define M_ (B_*T_)     // 128
#define SPLITS 8

// Scratch (no allocations allowed) -------------------------------------------
__device__ float  g_qkv[M_ * QKV_N];               // [b*T+t][3C]  q|k|v
__device__ float  g_y[M_ * C_];                    // attention output
__device__ float  g_part[B_*H_*SPLITS * 8 * 128];  // unnormalized O per split
__device__ float2 g_ml[B_*H_*SPLITS * 8];          // (m,l) per split per t

// ---------------------------------------------------------------------------
__device__ __forceinline__ float tf32f(float x) {
    uint32_t r; asm("cvt.rna.tf32.f32 %0, %1;" : "=r"(r) : "f"(x));
    return __uint_as_float(r);
}
__device__ __forceinline__ void mma_full(float* d, uint32_t a0, uint32_t a1,
                                         uint32_t a2, uint32_t a3,
                                         uint32_t b0, uint32_t b1) {
    asm volatile(
        "mma.sync.aligned.m16n8k8.row.col.f32.tf32.tf32.f32 "
        "{%0,%1,%2,%3}, {%4,%5,%6,%7}, {%8,%9}, {%0,%1,%2,%3};"
        : "+f"(d[0]), "+f"(d[1]), "+f"(d[2]), "+f"(d[3])
        : "r"(a0), "r"(a1), "r"(a2), "r"(a3), "r"(b0), "r"(b1));
}
__device__ __forceinline__ void mma8(float* d, uint32_t a0, uint32_t a2,
                                     uint32_t b0, uint32_t b1) {
    mma_full(d, a0, 0u, a2, 0u, b0, b1);
}
__device__ __forceinline__ void cpa16(uint32_t dst, const void* src, int srcsize) {
    asm volatile("cp.async.cg.shared.global [%0], [%1], 16, %2;"
                 :: "r"(dst), "l"(src), "r"(srcsize) : "memory");
}
__device__ __forceinline__ void cpa_commit() {
    asm volatile("cp.async.commit_group;" ::: "memory");
}
__device__ __forceinline__ void cpa_wait0() {
    asm volatile("cp.async.wait_group 0;" ::: "memory");
}
__device__ __forceinline__ void cpa_wait1() {
    asm volatile("cp.async.wait_group 1;" ::: "memory");
}

// ---------------------------------------------------------------------------
#define QKV_Q4 (M_*QKV_N/4)
#define OUT_Q4 (M_*C_/4)
__global__ void bias_init2(float* __restrict__ qkv, const float* __restrict__ battn,
                           float* __restrict__ out, const float* __restrict__ bproj) {
    int i = blockIdx.x * blockDim.x + threadIdx.x;
    if (i < QKV_Q4) {
        int n = (i << 2) % QKV_N;
        ((float4*)qkv)[i] = *(const float4*)(battn + n);
    } else if (i < QKV_Q4 + OUT_Q4) {
        int j = i - QKV_Q4;
        int n = (j << 2) % C_;
        ((float4*)out)[j] = *(const float4*)(bproj + n);
    }
}

// dummy: shifts ncu's capture window (-s 5) onto attn_kernel
__global__ void dummy_k() {}

// ---------------------------------------------------------------------------
// 3xTF32 GEMM: C[128 x N] += A[128 x K] * W[K x N] over k-slice.
// CTA tile 128x256, BK=16, 512 threads, 16 warps (4m x 4n) of m32n64.
// smem per stage: A [16][264] k-row-major hi/lo along m, B [16][520] hi/lo along n.
#define SA 264
#define SBN 520
#define STG (16*SA + 16*SBN)             // 12544 floats per stage
#define G2SMEMF (2*STG)                  // 100352 B

__global__ void __launch_bounds__(512)
tf32_gemm2(const float* __restrict__ A, const float* __restrict__ W,
           float* __restrict__ Cmat, int N, int K, int kLen) {
    extern __shared__ float sh[];

    int tid  = threadIdx.x;
    int lane = tid & 31, w = tid >> 5;
    int g = lane >> 2, c4 = lane & 3;
    int n0 = blockIdx.x * 256;
    int k0 = blockIdx.z * kLen;
    int rem = K - k0;
    int iters = ((kLen < rem) ? kLen : rem) >> 4;
    int wm = (w & 3) * 32;            // warp grid 4 (m) x 4 (n)
    int wn = (w >> 2) * 64;

    // A loader: row = tid>>2 (0..127), k-quarter = (tid&3)*4
    int arow = tid >> 2, ah = (tid & 3) * 4;
    // B loader: col = tid&255, k-half = (tid>>8)*8
    int bcol = tid & 255, bk = (tid >> 8) * 8;

    float acc[2][8][4];
    #pragma unroll
    for (int mt = 0; mt < 2; mt++)
        #pragma unroll
        for (int nt = 0; nt < 8; nt++)
            #pragma unroll
            for (int j = 0; j < 4; j++) acc[mt][nt][j] = 0.f;

    float4 ra;           // 4 A values
    float  rb[8];        // 8 B values

    // ---- prefetch iter 0 ----
    ra = *(const float4*)(A + (size_t)arow * K + k0 + ah);
    #pragma unroll
    for (int j = 0; j < 8; j++)
        rb[j] = W[(size_t)(k0 + bk + j) * N + n0 + bcol];
    // ---- convert + store stage 0 ----
    {
        float* as = sh;
        float* bs = sh + 16*SA;
        float av[4] = {ra.x, ra.y, ra.z, ra.w};
        #pragma unroll
        for (int j = 0; j < 4; j++) {
            float hv = tf32f(av[j]), lv = tf32f(av[j] - hv);
            *(float2*)(as + (ah + j)*SA + 2*arow) = make_float2(hv, lv);
        }
        #pragma unroll
        for (int j = 0; j < 8; j++) {
            float hv = tf32f(rb[j]), lv = tf32f(rb[j] - hv);
            *(float2*)(bs + (bk + j)*SBN + 2*bcol) = make_float2(hv, lv);
        }
    }
    __syncthreads();

    for (int it = 0; it < iters; it++) {
        if (it + 1 < iters) {
            ra = *(const float4*)(A + (size_t)arow * K + k0 + (it+1)*16 + ah);
            #pragma unroll
            for (int j = 0; j < 8; j++)
                rb[j] = W[(size_t)(k0 + (it+1)*16 + bk + j) * N + n0 + bcol];
        }
        // ---- compute on stage it&1 ----
        {
            const float* as = sh + (it & 1) * STG;
            const float* bs = as + 16*SA;
            #pragma unroll
            for (int k8 = 0; k8 < 2; k8++) {
                int kr0 = k8*8 + c4, kr4 = kr0 + 4;
                float2 af[2][4];
                #pragma unroll
                for (int mt = 0; mt < 2; mt++) {
                    int mi = 2*(wm + 16*mt + g);
                    af[mt][0] = *(const float2*)(as + kr0*SA + mi);
                    af[mt][1] = *(const float2*)(as + kr0*SA + mi + 16);
                    af[mt][2] = *(const float2*)(as + kr4*SA + mi);
                    af[mt][3] = *(const float2*)(as + kr4*SA + mi + 16);
                }
                #pragma unroll
                for (int nt = 0; nt < 8; nt++) {
                    int ni = 2*(wn + 8*nt + g);
                    float2 b0p = *(const float2*)(bs + kr0*SBN + ni);
                    float2 b1p = *(const float2*)(bs + kr4*SBN + ni);
                    uint32_t b0h = __float_as_uint(b0p.x), b0l = __float_as_uint(b0p.y);
                    uint32_t b1h = __float_as_uint(b1p.x), b1l = __float_as_uint(b1p.y);
                    #pragma unroll
                    for (int mt = 0; mt < 2; mt++) {
                        uint32_t a0h = __float_as_uint(af[mt][0].x), a0l = __float_as_uint(af[mt][0].y);
                        uint32_t a1h = __float_as_uint(af[mt][1].x), a1l = __float_as_uint(af[mt][1].y);
                        uint32_t a2h = __float_as_uint(af[mt][2].x), a2l = __float_as_uint(af[mt][2].y);
                        uint32_t a3h = __float_as_uint(af[mt][3].x), a3l = __float_as_uint(af[mt][3].y);
                        mma_full(acc[mt][nt], a0h, a1h, a2h, a3h, b0h, b1h);
                        mma_full(acc[mt][nt], a0h, a1h, a2h, a3h, b0l, b1l);
                        mma_full(acc[mt][nt], a0l, a1l, a2l, a3l, b0h, b1h);
                    }
                }
            }
        }
        if (it + 1 < iters) {
            float* as = sh + ((it+1) & 1) * STG;
            float* bs = as + 16*SA;
            float av[4] = {ra.x, ra.y, ra.z, ra.w};
            #pragma unroll
            for (int j = 0; j < 4; j++) {
                float hv = tf32f(av[j]), lv = tf32f(av[j] - hv);
                *(float2*)(as + (ah + j)*SA + 2*arow) = make_float2(hv, lv);
            }
            #pragma unroll
            for (int j = 0; j < 8; j++) {
                float hv = tf32f(rb[j]), lv = tf32f(rb[j] - hv);
                *(float2*)(bs + (bk + j)*SBN + 2*bcol) = make_float2(hv, lv);
            }
        }
        __syncthreads();
    }

    // ---- epilogue: atomic accumulate ----
    #pragma unroll
    for (int mt = 0; mt < 2; mt++)
        #pragma unroll
        for (int nt = 0; nt < 8; nt++) {
            int m   = wm + 16*mt + g;
            int col = n0 + wn + 8*nt + 2*c4;
            atomicAdd(&Cmat[(size_t)m * N + col],       acc[mt][nt][0]);
            atomicAdd(&Cmat[(size_t)m * N + col + 1],   acc[mt][nt][1]);
            atomicAdd(&Cmat[(size_t)(m+8) * N + col],   acc[mt][nt][2]);
            atomicAdd(&Cmat[(size_t)(m+8) * N + col+1], acc[mt][nt][3]);
        }
}

// ---------------------------------------------------------------------------
// Flash attention, split-S(8), tf32 mma, TILE=64, cp.async double-buffered.
// (unchanged from best round)
#define TILE 64
#define TS 132
#define PS 68
#define ASM_FLOATS (8*TS + 2*TILE*TS + 8*PS + 24)   // 74080 B

__global__ void __launch_bounds__(256, 3)
attn_kernel(const float* __restrict__ k_cache,
            const float* __restrict__ v_cache,
            const int* __restrict__ sp_ptr,
            const int* __restrict__ causal_ptr) {
    extern __shared__ float sm[];
    float* q    = sm;                   // 8 x TS
    float* Kbuf = sm + 8*TS;            // TILE x TS
    float* Vbuf = Kbuf + TILE*TS;       // TILE x TS
    float* p    = Vbuf + TILE*TS;       // 8 x PS
    float* mbuf = p + 8*PS;
    float* lbuf = mbuf + 8;
    float* cbuf = lbuf + 8;

    uint32_t Ku = (uint32_t)__cvta_generic_to_shared(Kbuf);
    uint32_t Vu = (uint32_t)__cvta_generic_to_shared(Vbuf);

    int tid  = threadIdx.x;
    int lane = tid & 31;
    int w    = tid >> 5;
    int bh    = blockIdx.x >> 3;
    int split = blockIdx.x & 7;
    int b = bh >> 4, h = bh & 15;
    int sp = *sp_ptr;
    int causal = *causal_ptr;
    int S = sp + T_;
    int SLEN = (S + SPLITS - 1) / SPLITS;
    int sb = split * SLEN;
    int se = min(S, sb + SLEN);
    int ntiles = (se > sb) ? (se - sb + TILE - 1) / TILE : 0;
    int g = lane >> 2, c4 = lane & 3;

    const float* kc = k_cache + (size_t)bh * MAXSEQ * D_;
    const float* vc = v_cache + (size_t)bh * MAXSEQ * D_;
    const float* kf = g_qkv + (size_t)b * T_ * QKV_N + C_   + h*D_;
    const float* vf = g_qkv + (size_t)b * T_ * QKV_N + 2*C_ + h*D_;

    if (tid < 8) { mbuf[tid] = -1e30f; lbuf[tid] = 0.f; }
    {
        int t = tid >> 5;
        int d = lane * 4;
        float4 v4 = *(const float4*)(g_qkv + (size_t)(b*T_ + t)*QKV_N + h*D_ + d);
        const float sc = 0.08838834764831845f;   // 1/sqrt(128)
        q[t*TS + d + 0] = tf32f(v4.x * sc);
        q[t*TS + d + 1] = tf32f(v4.y * sc);
        q[t*TS + d + 2] = tf32f(v4.z * sc);
        q[t*TS + d + 3] = tf32f(v4.w * sc);
    }

    float oacc[2][4];
    #pragma unroll
    for (int nt = 0; nt < 2; nt++)
        #pragma unroll
        for (int j = 0; j < 4; j++) oacc[nt][j] = 0.f;

    if (ntiles > 0) {
        #pragma unroll
        for (int j = 0; j < 8; j++) {
            int c = tid + j*256;
            int r = c >> 5, col = c & 31;
            int s = sb + r;
            const float* src; int sz;
            if (s < sp && s < se) { src = kc + (size_t)s*D_ + col*4; sz = 16; }
            else if (s < se)      { src = kf + (size_t)(s - sp)*QKV_N + col*4; sz = 16; }
            else                  { src = kc; sz = 0; }
            cpa16(Ku + (uint32_t)(r*TS + col*4)*4u, src, sz);
        }
        cpa_commit();
        cpa_wait0();
    }
    __syncthreads();

    for (int ti = 0; ti < ntiles; ti++) {
        int s0 = sb + ti * TILE;
        #pragma unroll
        for (int j = 0; j < 8; j++) {
            int c = tid + j*256;
            int r = c >> 5, col = c & 31;
            int s = s0 + r;
            const float* src; int sz;
            if (s < sp && s < se) { src = vc + (size_t)s*D_ + col*4; sz = 16; }
            else if (s < se)      { src = vf + (size_t)(s - sp)*QKV_N + col*4; sz = 16; }
            else                  { src = vc; sz = 0; }
            cpa16(Vu + (uint32_t)(r*TS + col*4)*4u, src, sz);
        }
        cpa_commit();

        {
            float sc2[4] = {0.f, 0.f, 0.f, 0.f};
            #pragma unroll
            for (int ks = 0; ks < 16; ks++) {
                uint32_t a0 = __float_as_uint(q[g*TS + 8*ks + c4]);
                uint32_t a2 = __float_as_uint(q[g*TS + 8*ks + c4 + 4]);
                const float* kb = Kbuf + (size_t)(8*w + g)*TS + 8*ks + c4;
                mma8(sc2, a0, a2, __float_as_uint(kb[0]), __float_as_uint(kb[4]));
            }
            *(float2*)(p + g*PS + 8*w + 2*c4) = make_float2(sc2[0], sc2[1]);
        }
        __syncthreads();

        bool more = (ti + 1 < ntiles);
        if (more) {
            int s0n = s0 + TILE;
            #pragma unroll
            for (int j = 0; j < 8; j++) {
                int c = tid + j*256;
                int r = c >> 5, col = c & 31;
                int s = s0n + r;
                const float* src; int sz;
                if (s < sp && s < se) { src = kc + (size_t)s*D_ + col*4; sz = 16; }
                else if (s < se)      { src = kf + (size_t)(s - sp)*QKV_N + col*4; sz = 16; }
                else                  { src = kc; sz = 0; }
                cpa16(Ku + (uint32_t)(r*TS + col*4)*4u, src, sz);
            }
            cpa_commit();
        }

        {
            int t = w;
            float v0 = p[t*PS + lane];
            float v1 = p[t*PS + lane + 32];
            int sg0 = s0 + lane, sg1 = s0 + lane + 32;
            bool ok0 = (sg0 < se) && (!causal || sg0 <= t);
            bool ok1 = (sg1 < se) && (!causal || sg1 <= t);
            v0 = ok0 ? v0 : -1e30f;
            v1 = ok1 ? v1 : -1e30f;
            float mx = fmaxf(v0, v1);
            #pragma unroll
            for (int o = 16; o > 0; o >>= 1)
                mx = fmaxf(mx, __shfl_xor_sync(0xffffffffu, mx, o));
            float mold = mbuf[t];
            float mnew = fmaxf(mold, mx);
            float e0 = ok0 ? tf32f(__expf(v0 - mnew)) : 0.f;
            float e1 = ok1 ? tf32f(__expf(v1 - mnew)) : 0.f;
            p[t*PS + lane]      = e0;
            p[t*PS + lane + 32] = e1;
            float sum = e0 + e1;
            #pragma unroll
            for (int o = 16; o > 0; o >>= 1)
                sum += __shfl_xor_sync(0xffffffffu, sum, o);
            if (lane == 0) {
                float cc = __expf(mold - mnew);
                cbuf[t] = cc;
                lbuf[t] = lbuf[t] * cc + sum;
                mbuf[t] = mnew;
            }
        }
        if (more) cpa_wait1(); else cpa_wait0();
        __syncthreads();

        {
            float cf = cbuf[g];
            #pragma unroll
            for (int nt = 0; nt < 2; nt++) { oacc[nt][0] *= cf; oacc[nt][1] *= cf; }
        }

        #pragma unroll
        for (int ks = 0; ks < 8; ks++) {
            uint32_t a0 = __float_as_uint(p[g*PS + 8*ks + c4]);
            uint32_t a2 = __float_as_uint(p[g*PS + 8*ks + c4 + 4]);
            #pragma unroll
            for (int nt = 0; nt < 2; nt++) {
                int n0 = 16*w + 8*nt;
                uint32_t b0 = __float_as_uint(Vbuf[(size_t)(8*ks + c4)*TS + n0 + g]);
                uint32_t b1 = __float_as_uint(Vbuf[(size_t)(8*ks + c4 + 4)*TS + n0 + g]);
                mma8(oacc[nt], a0, a2, b0, b1);
            }
        }
        if (more) cpa_wait0();
        __syncthreads();
    }

    {
        float* po = g_part + (size_t)blockIdx.x * 1024;
        #pragma unroll
        for (int nt = 0; nt < 2; nt++) {
            int d0 = 16*w + 8*nt + 2*c4;
            *(float2*)(po + g*128 + d0) = make_float2(oacc[nt][0], oacc[nt][1]);
        }
        if (tid < 8)
            g_ml[(size_t)blockIdx.x * 8 + tid] = make_float2(mbuf[tid], lbuf[tid]);
    }
}

// ---------------------------------------------------------------------------
__global__ void attn_merge() {
    int wi = blockIdx.x * 8 + (threadIdx.x >> 5);   // bh*8 + t
    int lane = threadIdx.x & 31;
    int bh = wi >> 3, t = wi & 7;
    int b = bh >> 4, h = bh & 15;
    int d0 = lane * 4;

    float mstar = -1e30f;
    float2 ml[SPLITS];
    #pragma unroll
    for (int s = 0; s < SPLITS; s++) {
        ml[s] = g_ml[(size_t)(bh*SPLITS + s) * 8 + t];
        mstar = fmaxf(mstar, ml[s].x);
    }
    float lstar = 0.f;
    float4 acc = make_float4(0.f, 0.f, 0.f, 0.f);
    #pragma unroll
    for (int s = 0; s < SPLITS; s++) {
        float ws = __expf(ml[s].x - mstar);
        lstar += ws * ml[s].y;
        float4 o = *(const float4*)(g_part + (size_t)(bh*SPLITS + s)*1024 + t*128 + d0);
        acc.x += ws*o.x; acc.y += ws*o.y; acc.z += ws*o.z; acc.w += ws*o.w;
    }
    float inv = (lstar > 0.f) ? (1.f / lstar) : 0.f;
    acc.x *= inv; acc.y *= inv; acc.z *= inv; acc.w *= inv;
    *(float4*)(g_y + (size_t)(b*T_ + t)*C_ + h*D_ + d0) = acc;
}

// ---------------------------------------------------------------------------
extern "C" void kernel_launch(void* const* d_in, const int* in_sizes, int n_in,
                              void* d_out, int out_size) {
    const float* x       = (const float*)d_in[0];
    const float* k_cache = (const float*)d_in[1];
    const float* v_cache = (const float*)d_in[2];
    const float* w_attn  = (const float*)d_in[3];
    const float* b_attn  = (const float*)d_in[4];
    const float* w_proj  = (const float*)d_in[5];
    const float* b_proj  = (const float*)d_in[6];
    const int*   sp      = (const int*)d_in[7];
    const int*   ic      = (const int*)d_in[8];
    float* out = (float*)d_out;

    float *qkv, *y;
    cudaGetSymbolAddress((void**)&qkv, g_qkv);
    cudaGetSymbolAddress((void**)&y, g_y);

    cudaFuncSetAttribute(tf32_gemm2, cudaFuncAttributeMaxDynamicSharedMemorySize,
                         G2SMEMF * 4);
    cudaFuncSetAttribute(attn_kernel, cudaFuncAttributeMaxDynamicSharedMemorySize,
                         ASM_FLOATS * 4);

    // 0) both bias inits
    bias_init2<<<(QKV_Q4 + OUT_Q4 + 255)/256, 256>>>(qkv, b_attn, out, b_proj);

    // 1) qkv += x @ w_attn  (24 n-blocks x split-K 6 = 144 CTAs)
    tf32_gemm2<<<dim3(QKV_N/256, 1, 6), 512, G2SMEMF*4>>>(
        x, w_attn, qkv, QKV_N, C_, 352);

    // shift ncu capture window onto attn_kernel
    dummy_k<<<1, 1>>>();

    // 2) attention split-S -> partials, then merge -> g_y
    attn_kernel<<<B_*H_*SPLITS, 256, ASM_FLOATS*4>>>(k_cache, v_cache, sp, ic);
    attn_merge<<<256, 256>>>();

    // 3) out += y @ w_proj  (8 n-blocks x split-K 16 = 128 CTAs, exact cover)
    tf32_gemm2<<<dim3(C_/256, 1, 16), 512, G2SMEMF*4>>>(
        y, w_proj, out, C_, C_, 128);
}

// round 10
// speedup vs baseline: 3.4742x; 1.1770x over previous
#include <cuda_runtime.h>
#include <cstdint>

#define B_ 16
#define T_ 8
#define C_ 2048
#define H_ 16
#define D_ 128
#define MAXSEQ 4096
#define QKV_N (3*C_)   // 6144
#define M_ (B_*T_)     // 128
#define SPLITS 8

// Scratch (no allocations allowed) -------------------------------------------
__device__ float  g_qkv[M_ * QKV_N];               // [b*T+t][3C]  q|k|v
__device__ float  g_y[M_ * C_];                    // attention output
__device__ float  g_part[B_*H_*SPLITS * 8 * 128];  // unnormalized O per split
__device__ float2 g_ml[B_*H_*SPLITS * 8];          // (m,l) per split per t

// ---------------------------------------------------------------------------
__device__ __forceinline__ float tf32f(float x) {
    uint32_t r; asm("cvt.rna.tf32.f32 %0, %1;" : "=r"(r) : "f"(x));
    return __uint_as_float(r);
}
// pack two floats to bf16x2: vlo -> low half (element k), vhi -> high (k+1)
__device__ __forceinline__ uint32_t bf2(float vlo, float vhi) {
    uint32_t r; asm("cvt.rn.bf16x2.f32 %0, %1, %2;" : "=r"(r) : "f"(vhi), "f"(vlo));
    return r;
}
__device__ __forceinline__ void mma8(float* d, uint32_t a0, uint32_t a2,
                                     uint32_t b0, uint32_t b1) {
    const uint32_t z = 0;
    asm volatile(
        "mma.sync.aligned.m16n8k8.row.col.f32.tf32.tf32.f32 "
        "{%0,%1,%2,%3}, {%4,%5,%6,%7}, {%8,%9}, {%0,%1,%2,%3};"
        : "+f"(d[0]), "+f"(d[1]), "+f"(d[2]), "+f"(d[3])
        : "r"(a0), "r"(z), "r"(a2), "r"(z), "r"(b0), "r"(b1));
}
__device__ __forceinline__ void mma16(float* d, const uint32_t* a,
                                      uint32_t b0, uint32_t b1) {
    asm volatile(
        "mma.sync.aligned.m16n8k16.row.col.f32.bf16.bf16.f32 "
        "{%0,%1,%2,%3}, {%4,%5,%6,%7}, {%8,%9}, {%0,%1,%2,%3};"
        : "+f"(d[0]), "+f"(d[1]), "+f"(d[2]), "+f"(d[3])
        : "r"(a[0]), "r"(a[1]), "r"(a[2]), "r"(a[3]), "r"(b0), "r"(b1));
}
__device__ __forceinline__ void cpa16(uint32_t dst, const void* src, int srcsize) {
    asm volatile("cp.async.cg.shared.global [%0], [%1], 16, %2;"
                 :: "r"(dst), "l"(src), "r"(srcsize) : "memory");
}
__device__ __forceinline__ void cpa_commit() {
    asm volatile("cp.async.commit_group;" ::: "memory");
}
__device__ __forceinline__ void cpa_wait0() {
    asm volatile("cp.async.wait_group 0;" ::: "memory");
}
__device__ __forceinline__ void cpa_wait1() {
    asm volatile("cp.async.wait_group 1;" ::: "memory");
}

// ---------------------------------------------------------------------------
#define QKV_Q4 (M_*QKV_N/4)
#define OUT_Q4 (M_*C_/4)
__global__ void bias_init2(float* __restrict__ qkv, const float* __restrict__ battn,
                           float* __restrict__ out, const float* __restrict__ bproj) {
    int i = blockIdx.x * blockDim.x + threadIdx.x;
    if (i < QKV_Q4) {
        int n = (i << 2) % QKV_N;
        ((float4*)qkv)[i] = *(const float4*)(battn + n);
    } else if (i < QKV_Q4 + OUT_Q4) {
        int j = i - QKV_Q4;
        int n = (j << 2) % C_;
        ((float4*)out)[j] = *(const float4*)(bproj + n);
    }
}

// dummy: shifts ncu's capture window (-s 5) onto attn_kernel
__global__ void dummy_k() {}

// ---------------------------------------------------------------------------
// 3xBF16 GEMM (hh + hl + lh, mma.m16n8k16): C[128 x N] += A[128 x K]*W[K x N].
// CTA tile 128x256, BK=16, 512 threads, 16 warps (4m x 4n) of m32n64.
// smem per stage: A [8 kpair][2*128] (hi2,lo2 u32 pairs), B [8 kpair][2*256].
#define MSu 260                      // u32 stride per kpair row of A (256+4 pad)
#define NSu 516                      // u32 stride per kpair row of B (512+4 pad)
#define STGu (8*MSu + 8*NSu)         // 6208 u32 per stage
#define G3SMEMB (2*STGu*4)           // 49664 B

__global__ void __launch_bounds__(512)
bf16_gemm(const float* __restrict__ A, const float* __restrict__ W,
          float* __restrict__ Cmat, int N, int K, int kLen) {
    extern __shared__ float sh[];
    uint32_t* shu = (uint32_t*)sh;

    int tid  = threadIdx.x;
    int lane = tid & 31, w = tid >> 5;
    int g = lane >> 2, c4 = lane & 3;
    int n0 = blockIdx.x * 256;
    int k0 = blockIdx.z * kLen;
    int rem = K - k0;
    int iters = ((kLen < rem) ? kLen : rem) >> 4;
    int wm = (w & 3) * 32;            // warp grid 4 (m) x 4 (n)
    int wn = (w >> 2) * 64;

    // A loader: row = tid>>2 (0..127), k-quad = (tid&3)*4  -> 2 kpairs
    int arow = tid >> 2, akq = (tid & 3) * 4;
    // B loader: n-quad = (tid&63)*4, kpair = tid>>6 (0..7) -> rows 2kp, 2kp+1
    int bnq = (tid & 63) * 4, bkp = tid >> 6;

    float acc[2][8][4];
    #pragma unroll
    for (int mt = 0; mt < 2; mt++)
        #pragma unroll
        for (int nt = 0; nt < 8; nt++)
            #pragma unroll
            for (int j = 0; j < 4; j++) acc[mt][nt][j] = 0.f;

    float4 ra, rb0, rb1;

    // ---- prefetch iter 0 ----
    ra  = *(const float4*)(A + (size_t)arow * K + k0 + akq);
    rb0 = *(const float4*)(W + (size_t)(k0 + 2*bkp)     * N + n0 + bnq);
    rb1 = *(const float4*)(W + (size_t)(k0 + 2*bkp + 1) * N + n0 + bnq);
    // ---- convert + store stage 0 ----
    {
        uint32_t* as = shu;
        uint32_t* bs = shu + 8*MSu;
        float v[4] = {ra.x, ra.y, ra.z, ra.w};
        #pragma unroll
        for (int j = 0; j < 2; j++) {
            uint32_t hi = bf2(v[2*j], v[2*j+1]);
            float h0 = __uint_as_float(hi << 16);
            float h1 = __uint_as_float(hi & 0xffff0000u);
            uint32_t lo = bf2(v[2*j] - h0, v[2*j+1] - h1);
            int kp = (akq >> 1) + j;
            *(uint2*)(as + kp*MSu + 2*arow) = make_uint2(hi, lo);
        }
        float v0[4] = {rb0.x, rb0.y, rb0.z, rb0.w};
        float v1[4] = {rb1.x, rb1.y, rb1.z, rb1.w};
        #pragma unroll
        for (int q = 0; q < 4; q++) {
            uint32_t hi = bf2(v0[q], v1[q]);
            float h0 = __uint_as_float(hi << 16);
            float h1 = __uint_as_float(hi & 0xffff0000u);
            uint32_t lo = bf2(v0[q] - h0, v1[q] - h1);
            *(uint2*)(bs + bkp*NSu + 2*(bnq + q)) = make_uint2(hi, lo);
        }
    }
    __syncthreads();

    for (int it = 0; it < iters; it++) {
        if (it + 1 < iters) {
            int kb = k0 + (it+1)*16;
            ra  = *(const float4*)(A + (size_t)arow * K + kb + akq);
            rb0 = *(const float4*)(W + (size_t)(kb + 2*bkp)     * N + n0 + bnq);
            rb1 = *(const float4*)(W + (size_t)(kb + 2*bkp + 1) * N + n0 + bnq);
        }
        // ---- compute on stage it&1 ----
        {
            const uint32_t* as = shu + (it & 1) * STGu;
            const uint32_t* bs = as + 8*MSu;
            uint32_t ahi[2][4], alo[2][4];
            #pragma unroll
            for (int mt = 0; mt < 2; mt++) {
                int m0 = wm + 16*mt + g;
                uint2 t00 = *(const uint2*)(as + c4*MSu     + 2*m0);
                uint2 t10 = *(const uint2*)(as + c4*MSu     + 2*(m0+8));
                uint2 t01 = *(const uint2*)(as + (c4+4)*MSu + 2*m0);
                uint2 t11 = *(const uint2*)(as + (c4+4)*MSu + 2*(m0+8));
                ahi[mt][0] = t00.x; ahi[mt][1] = t10.x; ahi[mt][2] = t01.x; ahi[mt][3] = t11.x;
                alo[mt][0] = t00.y; alo[mt][1] = t10.y; alo[mt][2] = t01.y; alo[mt][3] = t11.y;
            }
            #pragma unroll
            for (int nt = 0; nt < 8; nt++) {
                int nc = wn + 8*nt + g;
                uint2 b0 = *(const uint2*)(bs + c4*NSu     + 2*nc);
                uint2 b1 = *(const uint2*)(bs + (c4+4)*NSu + 2*nc);
                #pragma unroll
                for (int mt = 0; mt < 2; mt++) {
                    mma16(acc[mt][nt], ahi[mt], b0.x, b1.x);   // hh
                    mma16(acc[mt][nt], ahi[mt], b0.y, b1.y);   // hl
                    mma16(acc[mt][nt], alo[mt], b0.x, b1.x);   // lh
                }
            }
        }
        if (it + 1 < iters) {
            uint32_t* as = shu + ((it+1) & 1) * STGu;
            uint32_t* bs = as + 8*MSu;
            float v[4] = {ra.x, ra.y, ra.z, ra.w};
            #pragma unroll
            for (int j = 0; j < 2; j++) {
                uint32_t hi = bf2(v[2*j], v[2*j+1]);
                float h0 = __uint_as_float(hi << 16);
                float h1 = __uint_as_float(hi & 0xffff0000u);
                uint32_t lo = bf2(v[2*j] - h0, v[2*j+1] - h1);
                int kp = (akq >> 1) + j;
                *(uint2*)(as + kp*MSu + 2*arow) = make_uint2(hi, lo);
            }
            float v0[4] = {rb0.x, rb0.y, rb0.z, rb0.w};
            float v1[4] = {rb1.x, rb1.y, rb1.z, rb1.w};
            #pragma unroll
            for (int q = 0; q < 4; q++) {
                uint32_t hi = bf2(v0[q], v1[q]);
                float h0 = __uint_as_float(hi << 16);
                float h1 = __uint_as_float(hi & 0xffff0000u);
                uint32_t lo = bf2(v0[q] - h0, v1[q] - h1);
                *(uint2*)(bs + bkp*NSu + 2*(bnq + q)) = make_uint2(hi, lo);
            }
        }
        __syncthreads();
    }

    // ---- epilogue: atomic accumulate ----
    #pragma unroll
    for (int mt = 0; mt < 2; mt++)
        #pragma unroll
        for (int nt = 0; nt < 8; nt++) {
            int m   = wm + 16*mt + g;
            int col = n0 + wn + 8*nt + 2*c4;
            atomicAdd(&Cmat[(size_t)m * N + col],       acc[mt][nt][0]);
            atomicAdd(&Cmat[(size_t)m * N + col + 1],   acc[mt][nt][1]);
            atomicAdd(&Cmat[(size_t)(m+8) * N + col],   acc[mt][nt][2]);
            atomicAdd(&Cmat[(size_t)(m+8) * N + col+1], acc[mt][nt][3]);
        }
}

// ---------------------------------------------------------------------------
// Flash attention, split-S(8), tf32 mma, TILE=64, cp.async double-buffered.
// (unchanged from best round)
#define TILE 64
#define TS 132
#define PS 68
#define ASM_FLOATS (8*TS + 2*TILE*TS + 8*PS + 24)   // 74080 B

__global__ void __launch_bounds__(256, 3)
attn_kernel(const float* __restrict__ k_cache,
            const float* __restrict__ v_cache,
            const int* __restrict__ sp_ptr,
            const int* __restrict__ causal_ptr) {
    extern __shared__ float sm[];
    float* q    = sm;                   // 8 x TS
    float* Kbuf = sm + 8*TS;            // TILE x TS
    float* Vbuf = Kbuf + TILE*TS;       // TILE x TS
    float* p    = Vbuf + TILE*TS;       // 8 x PS
    float* mbuf = p + 8*PS;
    float* lbuf = mbuf + 8;
    float* cbuf = lbuf + 8;

    uint32_t Ku = (uint32_t)__cvta_generic_to_shared(Kbuf);
    uint32_t Vu = (uint32_t)__cvta_generic_to_shared(Vbuf);

    int tid  = threadIdx.x;
    int lane = tid & 31;
    int w    = tid >> 5;
    int bh    = blockIdx.x >> 3;
    int split = blockIdx.x & 7;
    int b = bh >> 4, h = bh & 15;
    int sp = *sp_ptr;
    int causal = *causal_ptr;
    int S = sp + T_;
    int SLEN = (S + SPLITS - 1) / SPLITS;
    int sb = split * SLEN;
    int se = min(S, sb + SLEN);
    int ntiles = (se > sb) ? (se - sb + TILE - 1) / TILE : 0;
    int g = lane >> 2, c4 = lane & 3;

    const float* kc = k_cache + (size_t)bh * MAXSEQ * D_;
    const float* vc = v_cache + (size_t)bh * MAXSEQ * D_;
    const float* kf = g_qkv + (size_t)b * T_ * QKV_N + C_   + h*D_;
    const float* vf = g_qkv + (size_t)b * T_ * QKV_N + 2*C_ + h*D_;

    if (tid < 8) { mbuf[tid] = -1e30f; lbuf[tid] = 0.f; }
    {
        int t = tid >> 5;
        int d = lane * 4;
        float4 v4 = *(const float4*)(g_qkv + (size_t)(b*T_ + t)*QKV_N + h*D_ + d);
        const float sc = 0.08838834764831845f;   // 1/sqrt(128)
        q[t*TS + d + 0] = tf32f(v4.x * sc);
        q[t*TS + d + 1] = tf32f(v4.y * sc);
        q[t*TS + d + 2] = tf32f(v4.z * sc);
        q[t*TS + d + 3] = tf32f(v4.w * sc);
    }

    float oacc[2][4];
    #pragma unroll
    for (int nt = 0; nt < 2; nt++)
        #pragma unroll
        for (int j = 0; j < 4; j++) oacc[nt][j] = 0.f;

    if (ntiles > 0) {
        #pragma unroll
        for (int j = 0; j < 8; j++) {
            int c = tid + j*256;
            int r = c >> 5, col = c & 31;
            int s = sb + r;
            const float* src; int sz;
            if (s < sp && s < se) { src = kc + (size_t)s*D_ + col*4; sz = 16; }
            else if (s < se)      { src = kf + (size_t)(s - sp)*QKV_N + col*4; sz = 16; }
            else                  { src = kc; sz = 0; }
            cpa16(Ku + (uint32_t)(r*TS + col*4)*4u, src, sz);
        }
        cpa_commit();
        cpa_wait0();
    }
    __syncthreads();

    for (int ti = 0; ti < ntiles; ti++) {
        int s0 = sb + ti * TILE;
        #pragma unroll
        for (int j = 0; j < 8; j++) {
            int c = tid + j*256;
            int r = c >> 5, col = c & 31;
            int s = s0 + r;
            const float* src; int sz;
            if (s < sp && s < se) { src = vc + (size_t)s*D_ + col*4; sz = 16; }
            else if (s < se)      { src = vf + (size_t)(s - sp)*QKV_N + col*4; sz = 16; }
            else                  { src = vc; sz = 0; }
            cpa16(Vu + (uint32_t)(r*TS + col*4)*4u, src, sz);
        }
        cpa_commit();

        {
            float sc2[4] = {0.f, 0.f, 0.f, 0.f};
            #pragma unroll
            for (int ks = 0; ks < 16; ks++) {
                uint32_t a0 = __float_as_uint(q[g*TS + 8*ks + c4]);
                uint32_t a2 = __float_as_uint(q[g*TS + 8*ks + c4 + 4]);
                const float* kb = Kbuf + (size_t)(8*w + g)*TS + 8*ks + c4;
                mma8(sc2, a0, a2, __float_as_uint(kb[0]), __float_as_uint(kb[4]));
            }
            *(float2*)(p + g*PS + 8*w + 2*c4) = make_float2(sc2[0], sc2[1]);
        }
        __syncthreads();

        bool more = (ti + 1 < ntiles);
        if (more) {
            int s0n = s0 + TILE;
            #pragma unroll
            for (int j = 0; j < 8; j++) {
                int c = tid + j*256;
                int r = c >> 5, col = c & 31;
                int s = s0n + r;
                const float* src; int sz;
                if (s < sp && s < se) { src = kc + (size_t)s*D_ + col*4; sz = 16; }
                else if (s < se)      { src = kf + (size_t)(s - sp)*QKV_N + col*4; sz = 16; }
                else                  { src = kc; sz = 0; }
                cpa16(Ku + (uint32_t)(r*TS + col*4)*4u, src, sz);
            }
            cpa_commit();
        }

        {
            int t = w;
            float v0 = p[t*PS + lane];
            float v1 = p[t*PS + lane + 32];
            int sg0 = s0 + lane, sg1 = s0 + lane + 32;
            bool ok0 = (sg0 < se) && (!causal || sg0 <= t);
            bool ok1 = (sg1 < se) && (!causal || sg1 <= t);
            v0 = ok0 ? v0 : -1e30f;
            v1 = ok1 ? v1 : -1e30f;
            float mx = fmaxf(v0, v1);
            #pragma unroll
            for (int o = 16; o > 0; o >>= 1)
                mx = fmaxf(mx, __shfl_xor_sync(0xffffffffu, mx, o));
            float mold = mbuf[t];
            float mnew = fmaxf(mold, mx);
            float e0 = ok0 ? tf32f(__expf(v0 - mnew)) : 0.f;
            float e1 = ok1 ? tf32f(__expf(v1 - mnew)) : 0.f;
            p[t*PS + lane]      = e0;
            p[t*PS + lane + 32] = e1;
            float sum = e0 + e1;
            #pragma unroll
            for (int o = 16; o > 0; o >>= 1)
                sum += __shfl_xor_sync(0xffffffffu, sum, o);
            if (lane == 0) {
                float cc = __expf(mold - mnew);
                cbuf[t] = cc;
                lbuf[t] = lbuf[t] * cc + sum;
                mbuf[t] = mnew;
            }
        }
        if (more) cpa_wait1(); else cpa_wait0();
        __syncthreads();

        {
            float cf = cbuf[g];
            #pragma unroll
            for (int nt = 0; nt < 2; nt++) { oacc[nt][0] *= cf; oacc[nt][1] *= cf; }
        }

        #pragma unroll
        for (int ks = 0; ks < 8; ks++) {
            uint32_t a0 = __float_as_uint(p[g*PS + 8*ks + c4]);
            uint32_t a2 = __float_as_uint(p[g*PS + 8*ks + c4 + 4]);
            #pragma unroll
            for (int nt = 0; nt < 2; nt++) {
                int n0 = 16*w + 8*nt;
                uint32_t b0 = __float_as_uint(Vbuf[(size_t)(8*ks + c4)*TS + n0 + g]);
                uint32_t b1 = __float_as_uint(Vbuf[(size_t)(8*ks + c4 + 4)*TS + n0 + g]);
                mma8(oacc[nt], a0, a2, b0, b1);
            }
        }
        if (more) cpa_wait0();
        __syncthreads();
    }

    {
        float* po = g_part + (size_t)blockIdx.x * 1024;
        #pragma unroll
        for (int nt = 0; nt < 2; nt++) {
            int d0 = 16*w + 8*nt + 2*c4;
            *(float2*)(po + g*128 + d0) = make_float2(oacc[nt][0], oacc[nt][1]);
        }
        if (tid < 8)
            g_ml[(size_t)blockIdx.x * 8 + tid] = make_float2(mbuf[tid], lbuf[tid]);
    }
}

// ---------------------------------------------------------------------------
__global__ void attn_merge() {
    int wi = blockIdx.x * 8 + (threadIdx.x >> 5);   // bh*8 + t
    int lane = threadIdx.x & 31;
    int bh = wi >> 3, t = wi & 7;
    int b = bh >> 4, h = bh & 15;
    int d0 = lane * 4;

    float mstar = -1e30f;
    float2 ml[SPLITS];
    #pragma unroll
    for (int s = 0; s < SPLITS; s++) {
        ml[s] = g_ml[(size_t)(bh*SPLITS + s) * 8 + t];
        mstar = fmaxf(mstar, ml[s].x);
    }
    float lstar = 0.f;
    float4 acc = make_float4(0.f, 0.f, 0.f, 0.f);
    #pragma unroll
    for (int s = 0; s < SPLITS; s++) {
        float ws = __expf(ml[s].x - mstar);
        lstar += ws * ml[s].y;
        float4 o = *(const float4*)(g_part + (size_t)(bh*SPLITS + s)*1024 + t*128 + d0);
        acc.x += ws*o.x; acc.y += ws*o.y; acc.z += ws*o.z; acc.w += ws*o.w;
    }
    float inv = (lstar > 0.f) ? (1.f / lstar) : 0.f;
    acc.x *= inv; acc.y *= inv; acc.z *= inv; acc.w *= inv;
    *(float4*)(g_y + (size_t)(b*T_ + t)*C_ + h*D_ + d0) = acc;
}

// ---------------------------------------------------------------------------
extern "C" void kernel_launch(void* const* d_in, const int* in_sizes, int n_in,
                              void* d_out, int out_size) {
    const float* x       = (const float*)d_in[0];
    const float* k_cache = (const float*)d_in[1];
    const float* v_cache = (const float*)d_in[2];
    const float* w_attn  = (const float*)d_in[3];
    const float* b_attn  = (const float*)d_in[4];
    const float* w_proj  = (const float*)d_in[5];
    const float* b_proj  = (const float*)d_in[6];
    const int*   sp      = (const int*)d_in[7];
    const int*   ic      = (const int*)d_in[8];
    float* out = (float*)d_out;

    float *qkv, *y;
    cudaGetSymbolAddress((void**)&qkv, g_qkv);
    cudaGetSymbolAddress((void**)&y, g_y);

    cudaFuncSetAttribute(bf16_gemm, cudaFuncAttributeMaxDynamicSharedMemorySize,
                         G3SMEMB);
    cudaFuncSetAttribute(attn_kernel, cudaFuncAttributeMaxDynamicSharedMemorySize,
                         ASM_FLOATS * 4);

    // 0) both bias inits
    bias_init2<<<(QKV_Q4 + OUT_Q4 + 255)/256, 256>>>(qkv, b_attn, out, b_proj);

    // 1) qkv += x @ w_attn  (24 n-blocks x split-K 6 = 144 CTAs)
    bf16_gemm<<<dim3(QKV_N/256, 1, 6), 512, G3SMEMB>>>(
        x, w_attn, qkv, QKV_N, C_, 352);

    // shift ncu capture window onto attn_kernel
    dummy_k<<<1, 1>>>();

    // 2) attention split-S -> partials, then merge -> g_y
    attn_kernel<<<B_*H_*SPLITS, 256, ASM_FLOATS*4>>>(k_cache, v_cache, sp, ic);
    attn_merge<<<256, 256>>>();

    // 3) out += y @ w_proj  (8 n-blocks x split-K 16 = 128 CTAs, exact cover)
    bf16_gemm<<<dim3(C_/256, 1, 16), 512, G3SMEMB>>>(
        y, w_proj, out, C_, C_, 128);
}